// round 1
// baseline (speedup 1.0000x reference)
#include <cuda_runtime.h>
#include <cstdint>

#define BB   32
#define TT   512
#define DD   256
#define FF   256
#define KK   3
#define MEL  2304
#define TOK  16
#define EPSF 1e-5f

// ---------------- scratch (__device__ globals: no allocation allowed) ----------------
__device__ unsigned long long g_wP1[(DD/2)*KK*FF];   // packed float2 weights conv1: [(d2*3+k)*F + f] = {w[f,2d2,k], w[f,2d2+1,k]}
__device__ unsigned long long g_wP2[(FF/2)*KK*FF];   // same for conv2
__device__ float g_h1[(size_t)BB*TT*FF];             // conv1 output (post LN+ReLU)
__device__ int   g_idx[BB*MEL];                      // gather index per output row, -1 = masked

// ---------------- packed fp32x2 FMA ----------------
__device__ __forceinline__ unsigned long long fma2(unsigned long long a,
                                                   unsigned long long b,
                                                   unsigned long long c) {
    unsigned long long d;
    asm("fma.rn.f32x2 %0, %1, %2, %3;" : "=l"(d) : "l"(a), "l"(b), "l"(c));
    return d;
}
__device__ __forceinline__ void unpack2(unsigned long long v, float& lo, float& hi) {
    asm("mov.b64 {%0, %1}, %2;" : "=f"(lo), "=f"(hi) : "l"(v));
}

// ---------------- weight repack ----------------
__global__ void prep_w(const float* __restrict__ w1, const float* __restrict__ w2) {
    int i = blockIdx.x * blockDim.x + threadIdx.x;
    const int N = (DD/2) * KK * FF;
    if (i >= N) return;
    int f  = i % FF;
    int r  = i / FF;
    int d2 = r / KK;
    int k  = r % KK;
    float2 a, b;
    a.x = w1[(f*DD + 2*d2    )*KK + k];
    a.y = w1[(f*DD + 2*d2 + 1)*KK + k];
    b.x = w2[(f*FF + 2*d2    )*KK + k];
    b.y = w2[(f*FF + 2*d2 + 1)*KK + k];
    g_wP1[i] = *reinterpret_cast<unsigned long long*>(&a);
    g_wP2[i] = *reinterpret_cast<unsigned long long*>(&b);
}

// ---------------- fused conv1d(K=3) + bias + LayerNorm + ReLU (+ linear for stage 2) ----------------
// One block = 16 tokens x all 256 channels. 256 threads, thread = out channel.
template<bool SECOND>
__global__ __launch_bounds__(256)
void conv_ln(const float* __restrict__ in0,        // stage1: x; stage2: unused (reads g_h1)
             const float* __restrict__ bias,
             const float* __restrict__ gamma,
             const float* __restrict__ beta,
             float* __restrict__ out,              // stage1: unused (writes g_h1); stage2: dur_pred
             const float* __restrict__ lin_w,
             const float* __restrict__ lin_b) {
    __shared__ float xs[(TOK+2)*DD];
    __shared__ float hs[TOK*FF];
    __shared__ float stats[TOK*2];

    const int f  = threadIdx.x;
    const int bx = blockIdx.x;
    const int b  = bx / (TT/TOK);
    const int t0 = (bx % (TT/TOK)) * TOK;

    const float* __restrict__ xin = SECOND ? (g_h1 + (size_t)b*TT*FF)
                                           : (in0 + (size_t)b*TT*DD);
    // load 18 input rows (with zero padding at sequence edges), coalesced
    #pragma unroll
    for (int r = 0; r < TOK+2; ++r) {
        int t = t0 + r - 1;
        xs[r*DD + f] = (t >= 0 && t < TT) ? xin[(size_t)t*DD + f] : 0.f;
    }
    __syncthreads();

    unsigned long long acc[TOK];
    #pragma unroll
    for (int t = 0; t < TOK; ++t) acc[t] = 0ull;

    const unsigned long long* __restrict__ wrow = (SECOND ? g_wP2 : g_wP1) + f;

    for (int d2 = 0; d2 < DD/2; ++d2) {
        unsigned long long xv[TOK+2];
        #pragma unroll
        for (int r = 0; r < TOK+2; ++r)
            xv[r] = *reinterpret_cast<const unsigned long long*>(&xs[r*DD + 2*d2]);
        unsigned long long w0 = wrow[(d2*3 + 0)*FF];
        unsigned long long w1 = wrow[(d2*3 + 1)*FF];
        unsigned long long w2 = wrow[(d2*3 + 2)*FF];
        #pragma unroll
        for (int t = 0; t < TOK; ++t) {
            acc[t] = fma2(xv[t],   w0, acc[t]);
            acc[t] = fma2(xv[t+1], w1, acc[t]);
            acc[t] = fma2(xv[t+2], w2, acc[t]);
        }
    }

    const float bf = bias[f];
    float vals[TOK];
    #pragma unroll
    for (int t = 0; t < TOK; ++t) {
        float lo, hi; unpack2(acc[t], lo, hi);
        vals[t] = lo + hi + bf;
        hs[t*FF + f] = vals[t];
    }
    __syncthreads();

    // per-token mean/var: warp w handles tokens 2w, 2w+1
    const int wid = f >> 5, lane = f & 31;
    #pragma unroll
    for (int j = 0; j < 2; ++j) {
        int tt = wid*2 + j;
        float s = 0.f, ss = 0.f;
        #pragma unroll
        for (int c = 0; c < 8; ++c) {
            float v = hs[tt*FF + lane + c*32];
            s += v; ss += v*v;
        }
        #pragma unroll
        for (int o = 16; o > 0; o >>= 1) {
            s  += __shfl_xor_sync(0xffffffffu, s,  o);
            ss += __shfl_xor_sync(0xffffffffu, ss, o);
        }
        if (lane == 0) {
            float mu  = s  * (1.f/FF);
            float var = ss * (1.f/FF) - mu*mu;
            stats[tt*2]     = mu;
            stats[tt*2 + 1] = rsqrtf(var + EPSF);
        }
    }
    __syncthreads();

    const float gf = gamma[f], btf = beta[f];
    if (!SECOND) {
        #pragma unroll
        for (int t = 0; t < TOK; ++t) {
            float mu = stats[t*2], rs = stats[t*2 + 1];
            float v = fmaf((vals[t] - mu) * rs, gf, btf);
            v = fmaxf(v, 0.f);
            g_h1[((size_t)b*TT + t0 + t)*FF + f] = v;
        }
    } else {
        const float lw = lin_w[f];
        #pragma unroll
        for (int t = 0; t < TOK; ++t) {
            float mu = stats[t*2], rs = stats[t*2 + 1];
            float v = fmaf((vals[t] - mu) * rs, gf, btf);
            v = fmaxf(v, 0.f);
            hs[t*FF + f] = v * lw;
        }
        __syncthreads();
        const float lb = lin_b[0];
        #pragma unroll
        for (int j = 0; j < 2; ++j) {
            int tt = wid*2 + j;
            float s = 0.f;
            #pragma unroll
            for (int c = 0; c < 8; ++c) s += hs[tt*FF + lane + c*32];
            #pragma unroll
            for (int o = 16; o > 0; o >>= 1) s += __shfl_xor_sync(0xffffffffu, s, o);
            if (lane == 0)
                out[b*TT + t0 + tt] = fmaxf(s + lb, 0.f);
        }
    }
}

// ---------------- cumsum + searchsorted index ----------------
__global__ void cum_idx(const int* __restrict__ target) {
    __shared__ int cs[TT];
    const int b = blockIdx.x;
    const int t = threadIdx.x;   // 512 threads
    cs[t] = target[b*TT + t];
    __syncthreads();
    for (int off = 1; off < TT; off <<= 1) {
        int add = (t >= off) ? cs[t - off] : 0;
        __syncthreads();
        cs[t] += add;
        __syncthreads();
    }
    const int total = cs[TT - 1];
    for (int to = t; to < MEL; to += TT) {
        int lo = 0, hi = TT;
        while (lo < hi) {
            int mid = (lo + hi) >> 1;
            if (cs[mid] <= to) lo = mid + 1; else hi = mid;
        }
        g_idx[b*MEL + to] = (to < total) ? min(lo, TT - 1) : -1;
    }
}

// ---------------- gather (length regulation) ----------------
__global__ void gather_k(const float* __restrict__ x, float* __restrict__ out) {
    const long long i  = (long long)blockIdx.x * blockDim.x + threadIdx.x;
    const long long N4 = (long long)BB * MEL * (DD/4);
    if (i >= N4) return;
    const int  c4  = (int)(i & 63);
    const long long row = i >> 6;           // b*MEL + to
    const int  b   = (int)(row / MEL);
    const int  idx = g_idx[row];
    float4 v = make_float4(0.f, 0.f, 0.f, 0.f);
    if (idx >= 0)
        v = reinterpret_cast<const float4*>(x)[((long long)b*TT + idx)*(DD/4) + c4];
    reinterpret_cast<float4*>(out)[i] = v;
}

// ---------------- launch ----------------
extern "C" void kernel_launch(void* const* d_in, const int* in_sizes, int n_in,
                              void* d_out, int out_size) {
    // mel_max_length may or may not appear as a size-1 input between target and conv1_w
    int base = 2;
    if (n_in >= 13 && in_sizes[2] == 1) base = 3;

    const float* x      = (const float*)d_in[0];
    const int*   target = (const int*)  d_in[1];
    const float* c1w = (const float*)d_in[base + 0];
    const float* c1b = (const float*)d_in[base + 1];
    const float* l1g = (const float*)d_in[base + 2];
    const float* l1b = (const float*)d_in[base + 3];
    const float* c2w = (const float*)d_in[base + 4];
    const float* c2b = (const float*)d_in[base + 5];
    const float* l2g = (const float*)d_in[base + 6];
    const float* l2b = (const float*)d_in[base + 7];
    const float* lw  = (const float*)d_in[base + 8];
    const float* lb  = (const float*)d_in[base + 9];

    float* out = (float*)d_out;
    float* dur = out + (size_t)BB * MEL * DD;

    const int NW = (DD/2)*KK*FF;
    prep_w<<<(NW + 255)/256, 256>>>(c1w, c2w);

    conv_ln<false><<<BB*(TT/TOK), 256>>>(x, c1b, l1g, l1b, nullptr, lw, lb);
    conv_ln<true ><<<BB*(TT/TOK), 256>>>(nullptr, c2b, l2g, l2b, dur, lw, lb);

    cum_idx<<<BB, TT>>>(target);

    const long long N4 = (long long)BB * MEL * (DD/4);
    gather_k<<<(int)((N4 + 255)/256), 256>>>(x, out);
}

// round 5
// speedup vs baseline: 1.3090x; 1.3090x over previous
#include <cuda_runtime.h>
#include <cuda_bf16.h>
#include <mma.h>
#include <cstdint>

using namespace nvcuda;

#define BB   32
#define TT   512
#define DD   256
#define FF   256
#define MEL  2304
#define EPSF 1e-5f

#define TPB    256      // 8 warps
#define NCHUNK 24       // K=768 in chunks of 32
#define MTILE  64       // tokens per block
#define NTILES 8        // tiles per batch

// ---------------- device scratch ----------------
__device__ __align__(128) __nv_bfloat16 g_xpad_hi [(size_t)BB*(TT+2)*DD];
__device__ __align__(128) __nv_bfloat16 g_xpad_lo [(size_t)BB*(TT+2)*DD];
__device__ __align__(128) __nv_bfloat16 g_h1_hi   [(size_t)BB*(TT+2)*FF];
__device__ __align__(128) __nv_bfloat16 g_h1_lo   [(size_t)BB*(TT+2)*FF];
__device__ __align__(128) __nv_bfloat16 g_wB_hi   [2*768*256];   // [stage][kcol][f]
__device__ __align__(128) __nv_bfloat16 g_wB_lo   [2*768*256];
__device__ int g_idx[BB*MEL];

// ---------------- smem layout (bytes) ----------------
// A_hi: 2 x 64x40 bf16  @0      (5120 each)
// A_lo: 2 x 64x40 bf16  @10240
// B_hi: 2 x 32x264 bf16 @20480  (16896 each)
// B_lo: 2 x 32x264 bf16 @54272
// C   : 64x264 f32      @0      (67584, overlaps A/B after MMA phase)
// par : 1024 f32        @88064
#define OFF_ALO  10240
#define OFF_BHI  20480
#define OFF_BLO  54272
#define OFF_PAR  88064
#define SMEM_BYTES 92160
#define A_STRIDE 40
#define B_STRIDE 264
#define C_STRIDE 264

__device__ __forceinline__ uint32_t smem_u32(const void* p) {
    uint32_t a;
    asm("{ .reg .u64 t; cvta.to.shared.u64 t, %1; cvt.u32.u64 %0, t; }" : "=r"(a) : "l"(p));
    return a;
}
__device__ __forceinline__ void cp16(uint32_t dst, const void* src) {
    asm volatile("cp.async.cg.shared.global [%0], [%1], 16;" :: "r"(dst), "l"(src));
}
__device__ __forceinline__ void cp_commit() { asm volatile("cp.async.commit_group;" ::: "memory"); }
template<int N> __device__ __forceinline__ void cp_wait() { asm volatile("cp.async.wait_group %0;" :: "n"(N) : "memory"); }

// ---------------- prep ----------------
__global__ void prep_x(const float* __restrict__ x) {
    const int NTOT = BB*(TT+2)*DD;
    for (int i = blockIdx.x*blockDim.x + threadIdx.x; i < NTOT; i += gridDim.x*blockDim.x) {
        int d   = i & (DD-1);
        int row = i >> 8;
        int t   = row % (TT+2);
        int b   = row / (TT+2);
        float v = (t == 0 || t == TT+1) ? 0.f : x[((size_t)(b*TT + t - 1))*DD + d];
        __nv_bfloat16 hi = __float2bfloat16(v);
        g_xpad_hi[i] = hi;
        g_xpad_lo[i] = __float2bfloat16(v - __bfloat162float(hi));
    }
}
__global__ void prep_w(const float* __restrict__ w1, const float* __restrict__ w2) {
    const int NW = 2*768*256;
    for (int i = blockIdx.x*blockDim.x + threadIdx.x; i < NW; i += gridDim.x*blockDim.x) {
        int f    = i & 255;
        int rest = i >> 8;
        int kcol = rest % 768;
        int st   = rest / 768;
        int k    = kcol >> 8;
        int d    = kcol & 255;
        const float* w = st ? w2 : w1;
        float v = w[(f*DD + d)*3 + k];
        __nv_bfloat16 hi = __float2bfloat16(v);
        g_wB_hi[i] = hi;
        g_wB_lo[i] = __float2bfloat16(v - __bfloat162float(hi));
    }
    // zero padded edge rows of h1
    for (int i = blockIdx.x*blockDim.x + threadIdx.x; i < 2*BB*FF; i += gridDim.x*blockDim.x) {
        int d = i & (FF-1);
        int r = i >> 8;
        int b = r >> 1;
        int t = (r & 1) ? (TT+1) : 0;
        size_t o = ((size_t)(b*(TT+2) + t))*FF + d;
        g_h1_hi[o] = __float2bfloat16(0.f);
        g_h1_lo[o] = __float2bfloat16(0.f);
    }
}

// ---------------- fused conv(K=3) split-bf16 WMMA GEMM + bias + LN + ReLU (+linear) ----------------
template<int STAGE>
__global__ __launch_bounds__(TPB)
void conv_wmma(const float* __restrict__ bias,
               const float* __restrict__ gamma,
               const float* __restrict__ beta,
               const float* __restrict__ lin_w,
               const float* __restrict__ lin_b,
               float* __restrict__ dur_out) {
    extern __shared__ char smem[];
    const uint32_t sbase = smem_u32(smem);
    const int tid  = threadIdx.x;
    const int wid  = tid >> 5;
    const int lane = tid & 31;
    const int b    = blockIdx.x >> 3;
    const int t0   = (blockIdx.x & 7) * MTILE;

    const __nv_bfloat16* __restrict__ srcH = STAGE ? g_h1_hi : g_xpad_hi;
    const __nv_bfloat16* __restrict__ srcL = STAGE ? g_h1_lo : g_xpad_lo;
    float* Cs  = (float*)smem;
    float* par = (float*)(smem + OFF_PAR);

    // 256 threads, 256 channels: each thread stages exactly its own element
    par[tid]       = bias [tid];
    par[256 + tid] = gamma[tid];
    par[512 + tid] = beta [tid];
    par[768 + tid] = STAGE ? lin_w[tid] : 0.f;

    auto load_chunk = [&](int c) {
        const int buf = c & 1;
        const int k   = c >> 3;
        const int d0  = (c & 7) * 32;
        const uint32_t sAh = sbase + buf*5120;
        const uint32_t sAl = sbase + OFF_ALO + buf*5120;
        const uint32_t sBh = sbase + OFF_BHI + buf*16896;
        const uint32_t sBl = sbase + OFF_BLO + buf*16896;
        // A: 64 rows x 32 cols, 4 x 16B per row -> 256 cp16 each for hi/lo
        {
            int r = tid >> 2, seg = tid & 3;
            size_t go = ((size_t)(b*(TT+2) + t0 + k + r))*DD + d0 + seg*8;
            uint32_t so = r*(A_STRIDE*2) + seg*16;
            cp16(sAh + so, srcH + go);
            cp16(sAl + so, srcL + go);
        }
        // B: 32 rows x 256 cols, 32 x 16B per row -> 1024 cp16 each for hi/lo
        {
            const size_t bbase = ((size_t)(STAGE*768 + c*32))*256;
            #pragma unroll
            for (int it = 0; it < 4; ++it) {
                int u = tid + it*TPB;
                int r = u >> 5, seg = u & 31;
                size_t go = bbase + (size_t)r*256 + seg*8;
                uint32_t so = r*(B_STRIDE*2) + seg*16;
                cp16(sBh + so, g_wB_hi + go);
                cp16(sBl + so, g_wB_lo + go);
            }
        }
        cp_commit();
    };

    // warp tile: 32 tokens x 64 channels; 2 warps (M) x 4 warps (N)
    const int wm = wid & 1;
    const int wn = wid >> 1;

    wmma::fragment<wmma::accumulator, 16, 16, 16, float> acc[2][4];
    #pragma unroll
    for (int i = 0; i < 2; ++i)
        #pragma unroll
        for (int j = 0; j < 4; ++j)
            wmma::fill_fragment(acc[i][j], 0.f);

    load_chunk(0);
    load_chunk(1);

    for (int c = 0; c < NCHUNK; ++c) {
        if (c < NCHUNK - 1) cp_wait<1>(); else cp_wait<0>();
        __syncthreads();
        const int buf = c & 1;
        const __nv_bfloat16* Ah = (const __nv_bfloat16*)(smem + buf*5120);
        const __nv_bfloat16* Al = (const __nv_bfloat16*)(smem + OFF_ALO + buf*5120);
        const __nv_bfloat16* Bh = (const __nv_bfloat16*)(smem + OFF_BHI + buf*16896);
        const __nv_bfloat16* Bl = (const __nv_bfloat16*)(smem + OFF_BLO + buf*16896);
        #pragma unroll
        for (int ks = 0; ks < 2; ++ks) {
            wmma::fragment<wmma::matrix_a, 16, 16, 16, __nv_bfloat16, wmma::row_major> ah[2], al[2];
            #pragma unroll
            for (int i = 0; i < 2; ++i) {
                wmma::load_matrix_sync(ah[i], Ah + (wm*32 + i*16)*A_STRIDE + ks*16, A_STRIDE);
                wmma::load_matrix_sync(al[i], Al + (wm*32 + i*16)*A_STRIDE + ks*16, A_STRIDE);
            }
            #pragma unroll
            for (int j = 0; j < 4; ++j) {
                wmma::fragment<wmma::matrix_b, 16, 16, 16, __nv_bfloat16, wmma::row_major> bh, bl;
                wmma::load_matrix_sync(bh, Bh + (ks*16)*B_STRIDE + wn*64 + j*16, B_STRIDE);
                wmma::load_matrix_sync(bl, Bl + (ks*16)*B_STRIDE + wn*64 + j*16, B_STRIDE);
                #pragma unroll
                for (int i = 0; i < 2; ++i) {
                    wmma::mma_sync(acc[i][j], ah[i], bh, acc[i][j]);
                    wmma::mma_sync(acc[i][j], ah[i], bl, acc[i][j]);
                    wmma::mma_sync(acc[i][j], al[i], bh, acc[i][j]);
                }
            }
        }
        __syncthreads();
        if (c + 2 < NCHUNK) load_chunk(c + 2);
    }

    // store accumulators to smem (C overlaps A/B buffers; MMA phase done)
    __syncthreads();
    #pragma unroll
    for (int i = 0; i < 2; ++i)
        #pragma unroll
        for (int j = 0; j < 4; ++j)
            wmma::store_matrix_sync(Cs + (size_t)(wm*32 + i*16)*C_STRIDE + wn*64 + j*16,
                                    acc[i][j], C_STRIDE, wmma::mem_row_major);
    __syncthreads();

    // epilogue: each warp handles 8 token rows
    #pragma unroll
    for (int rr = 0; rr < 8; ++rr) {
        const int row = wid*8 + rr;
        float v[8];
        float s = 0.f, ss = 0.f;
        #pragma unroll
        for (int j = 0; j < 8; ++j) {
            v[j] = Cs[(size_t)row*C_STRIDE + lane + j*32] + par[lane + j*32];
            s  += v[j];
            ss += v[j]*v[j];
        }
        #pragma unroll
        for (int o = 16; o > 0; o >>= 1) {
            s  += __shfl_xor_sync(0xffffffffu, s,  o);
            ss += __shfl_xor_sync(0xffffffffu, ss, o);
        }
        const float mu = s * (1.f/FF);
        const float rs = rsqrtf(ss * (1.f/FF) - mu*mu + EPSF);

        if (!STAGE) {
            size_t ro = ((size_t)(b*(TT+2) + t0 + 1 + row))*FF;
            #pragma unroll
            for (int j = 0; j < 8; ++j) {
                int cch = lane + j*32;
                float w = fmaf((v[j] - mu)*rs, par[256 + cch], par[512 + cch]);
                w = fmaxf(w, 0.f);
                __nv_bfloat16 hi = __float2bfloat16(w);
                g_h1_hi[ro + cch] = hi;
                g_h1_lo[ro + cch] = __float2bfloat16(w - __bfloat162float(hi));
            }
        } else {
            float dot = 0.f;
            #pragma unroll
            for (int j = 0; j < 8; ++j) {
                int cch = lane + j*32;
                float w = fmaf((v[j] - mu)*rs, par[256 + cch], par[512 + cch]);
                dot = fmaf(fmaxf(w, 0.f), par[768 + cch], dot);
            }
            #pragma unroll
            for (int o = 16; o > 0; o >>= 1)
                dot += __shfl_xor_sync(0xffffffffu, dot, o);
            if (lane == 0)
                dur_out[b*TT + t0 + row] = fmaxf(dot + lin_b[0], 0.f);
        }
    }
}

// ---------------- cumsum + searchsorted ----------------
__global__ void cum_idx(const int* __restrict__ target) {
    __shared__ int cs[TT];
    __shared__ int wsum[16];
    const int b = blockIdx.x, t = threadIdx.x;
    const int wid = t >> 5, lid = t & 31;
    int sc = target[b*TT + t];
    #pragma unroll
    for (int o = 1; o < 32; o <<= 1) {
        int n = __shfl_up_sync(0xffffffffu, sc, o);
        if (lid >= o) sc += n;
    }
    if (lid == 31) wsum[wid] = sc;
    __syncthreads();
    if (wid == 0 && lid < 16) {
        int w = wsum[lid];
        #pragma unroll
        for (int o = 1; o < 16; o <<= 1) {
            int n = __shfl_up_sync(0xffffu, w, o);
            if (lid >= o) w += n;
        }
        wsum[lid] = w;
    }
    __syncthreads();
    cs[t] = sc + (wid ? wsum[wid-1] : 0);
    __syncthreads();
    const int total = cs[TT-1];
    for (int to = t; to < MEL; to += TT) {
        int lo = 0, hi = TT;
        while (lo < hi) {
            int mid = (lo + hi) >> 1;
            if (cs[mid] <= to) lo = mid + 1; else hi = mid;
        }
        g_idx[b*MEL + to] = (to < total) ? min(lo, TT-1) : -1;
    }
}

// ---------------- gather ----------------
__global__ void gather_k(const float* __restrict__ x, float* __restrict__ out) {
    const long long i  = (long long)blockIdx.x * blockDim.x + threadIdx.x;
    const long long N4 = (long long)BB * MEL * (DD/4);
    if (i >= N4) return;
    const int c4 = (int)(i & 63);
    const long long row = i >> 6;
    const int b   = (int)(row / MEL);
    const int idx = g_idx[row];
    float4 v = make_float4(0.f, 0.f, 0.f, 0.f);
    if (idx >= 0)
        v = reinterpret_cast<const float4*>(x)[((long long)b*TT + idx)*(DD/4) + c4];
    reinterpret_cast<float4*>(out)[i] = v;
}

// ---------------- launch ----------------
extern "C" void kernel_launch(void* const* d_in, const int* in_sizes, int n_in,
                              void* d_out, int out_size) {
    int base = 2;
    if (n_in >= 13 && in_sizes[2] == 1) base = 3;

    const float* x      = (const float*)d_in[0];
    const int*   target = (const int*)  d_in[1];
    const float* c1w = (const float*)d_in[base + 0];
    const float* c1b = (const float*)d_in[base + 1];
    const float* l1g = (const float*)d_in[base + 2];
    const float* l1b = (const float*)d_in[base + 3];
    const float* c2w = (const float*)d_in[base + 4];
    const float* c2b = (const float*)d_in[base + 5];
    const float* l2g = (const float*)d_in[base + 6];
    const float* l2b = (const float*)d_in[base + 7];
    const float* lw  = (const float*)d_in[base + 8];
    const float* lb  = (const float*)d_in[base + 9];

    float* out = (float*)d_out;
    float* dur = out + (size_t)BB * MEL * DD;

    cudaFuncSetAttribute(conv_wmma<0>, cudaFuncAttributeMaxDynamicSharedMemorySize, SMEM_BYTES);
    cudaFuncSetAttribute(conv_wmma<1>, cudaFuncAttributeMaxDynamicSharedMemorySize, SMEM_BYTES);

    prep_x<<<512, 256>>>(x);
    prep_w<<<512, 256>>>(c1w, c2w);
    cum_idx<<<BB, TT>>>(target);

    const long long N4 = (long long)BB * MEL * (DD/4);
    gather_k<<<(int)((N4 + 255)/256), 256>>>(x, out);

    conv_wmma<0><<<BB*NTILES, TPB, SMEM_BYTES>>>(c1b, l1g, l1b, lw, lb, nullptr);
    conv_wmma<1><<<BB*NTILES, TPB, SMEM_BYTES>>>(c2b, l2g, l2b, lw, lb, dur);
}

// round 6
// speedup vs baseline: 1.5590x; 1.1910x over previous
#include <cuda_runtime.h>
#include <cuda_bf16.h>
#include <mma.h>
#include <cstdint>

using namespace nvcuda;

#define BB   32
#define TT   512
#define DD   256
#define FF   256
#define MEL  2304
#define EPSF 1e-5f

#define TPB    512      // 16 warps
#define NCHUNK 24       // K=768 in chunks of 32
#define MTILE  128      // tokens per block
#define NTILES 4        // tiles per batch -> 128 blocks total

// ---------------- device scratch ----------------
__device__ __align__(128) __nv_bfloat16 g_xpad_hi [(size_t)BB*(TT+2)*DD];
__device__ __align__(128) __nv_bfloat16 g_xpad_lo [(size_t)BB*(TT+2)*DD];
__device__ __align__(128) __nv_bfloat16 g_h1_hi   [(size_t)BB*(TT+2)*FF];
__device__ __align__(128) __nv_bfloat16 g_h1_lo   [(size_t)BB*(TT+2)*FF];
__device__ __align__(128) __nv_bfloat16 g_wB_hi   [2*768*256];   // [stage][kcol][f]
__device__ __align__(128) __nv_bfloat16 g_wB_lo   [2*768*256];
__device__ int g_idx[BB*MEL];

// ---------------- smem layout (bytes) ----------------
// 3 stages x 54272:
//   A_hi 128x40 bf16 @ +0      (10240)
//   A_lo 128x40 bf16 @ +10240  (10240)
//   B_hi 32x264 bf16 @ +20480  (16896)
//   B_lo 32x264 bf16 @ +37376  (16896)
// C 128x264 f32 @0 (135168, overlaps stages after MMA phase)
// par 1024 f32 @162816
#define STAGE_BYTES 54272
#define OFF_ALO  10240
#define OFF_BHI  20480
#define OFF_BLO  37376
#define OFF_PAR  162816
#define SMEM_BYTES 166912
#define A_STRIDE 40
#define B_STRIDE 264
#define C_STRIDE 264

__device__ __forceinline__ uint32_t smem_u32(const void* p) {
    uint32_t a;
    asm("{ .reg .u64 t; cvta.to.shared.u64 t, %1; cvt.u32.u64 %0, t; }" : "=r"(a) : "l"(p));
    return a;
}
__device__ __forceinline__ void cp16(uint32_t dst, const void* src) {
    asm volatile("cp.async.cg.shared.global [%0], [%1], 16;" :: "r"(dst), "l"(src));
}
__device__ __forceinline__ void cp_commit() { asm volatile("cp.async.commit_group;" ::: "memory"); }
template<int N> __device__ __forceinline__ void cp_wait() { asm volatile("cp.async.wait_group %0;" :: "n"(N) : "memory"); }

// ---------------- prep ----------------
__global__ void prep_x(const float* __restrict__ x) {
    const int NTOT = BB*(TT+2)*DD;
    for (int i = blockIdx.x*blockDim.x + threadIdx.x; i < NTOT; i += gridDim.x*blockDim.x) {
        int d   = i & (DD-1);
        int row = i >> 8;
        int t   = row % (TT+2);
        int b   = row / (TT+2);
        float v = (t == 0 || t == TT+1) ? 0.f : x[((size_t)(b*TT + t - 1))*DD + d];
        __nv_bfloat16 hi = __float2bfloat16(v);
        g_xpad_hi[i] = hi;
        g_xpad_lo[i] = __float2bfloat16(v - __bfloat162float(hi));
    }
}
__global__ void prep_w(const float* __restrict__ w1, const float* __restrict__ w2) {
    const int NW = 2*768*256;
    for (int i = blockIdx.x*blockDim.x + threadIdx.x; i < NW; i += gridDim.x*blockDim.x) {
        int f    = i & 255;
        int rest = i >> 8;
        int kcol = rest % 768;
        int st   = rest / 768;
        int k    = kcol >> 8;
        int d    = kcol & 255;
        const float* w = st ? w2 : w1;
        float v = w[(f*DD + d)*3 + k];
        __nv_bfloat16 hi = __float2bfloat16(v);
        g_wB_hi[i] = hi;
        g_wB_lo[i] = __float2bfloat16(v - __bfloat162float(hi));
    }
    for (int i = blockIdx.x*blockDim.x + threadIdx.x; i < 2*BB*FF; i += gridDim.x*blockDim.x) {
        int d = i & (FF-1);
        int r = i >> 8;
        int b = r >> 1;
        int t = (r & 1) ? (TT+1) : 0;
        size_t o = ((size_t)(b*(TT+2) + t))*FF + d;
        g_h1_hi[o] = __float2bfloat16(0.f);
        g_h1_lo[o] = __float2bfloat16(0.f);
    }
}

// ---------------- fused conv(K=3) split-bf16 WMMA GEMM + bias + LN + ReLU (+linear) ----------------
template<int STAGE>
__global__ __launch_bounds__(TPB, 1)
void conv_wmma(const float* __restrict__ bias,
               const float* __restrict__ gamma,
               const float* __restrict__ beta,
               const float* __restrict__ lin_w,
               const float* __restrict__ lin_b,
               float* __restrict__ dur_out) {
    extern __shared__ char smem[];
    const uint32_t sbase = smem_u32(smem);
    const int tid  = threadIdx.x;
    const int wid  = tid >> 5;
    const int lane = tid & 31;
    const int b    = blockIdx.x >> 2;
    const int t0   = (blockIdx.x & 3) * MTILE;

    const __nv_bfloat16* __restrict__ srcH = STAGE ? g_h1_hi : g_xpad_hi;
    const __nv_bfloat16* __restrict__ srcL = STAGE ? g_h1_lo : g_xpad_lo;
    float* Cs  = (float*)smem;
    float* par = (float*)(smem + OFF_PAR);

    if (tid < 256) {
        par[tid]       = bias [tid];
        par[256 + tid] = gamma[tid];
        par[512 + tid] = beta [tid];
        par[768 + tid] = STAGE ? lin_w[tid] : 0.f;
    }

    auto load_chunk = [&](int c) {
        const uint32_t st = sbase + (uint32_t)(c % 3) * STAGE_BYTES;
        const int k   = c >> 3;
        const int d0  = (c & 7) * 32;
        // A: 128 rows x 32 cols, 4 x 16B segs per row -> 512 cp16 each for hi/lo
        {
            int r = tid >> 2, seg = tid & 3;
            size_t go = ((size_t)(b*(TT+2) + t0 + k + r))*DD + d0 + seg*8;
            uint32_t so = r*(A_STRIDE*2) + seg*16;
            cp16(st + so, srcH + go);
            cp16(st + OFF_ALO + so, srcL + go);
        }
        // B: 32 rows x 256 cols, 32 x 16B segs per row -> 1024 cp16 each for hi/lo
        {
            const size_t bbase = ((size_t)(STAGE*768 + c*32))*256;
            #pragma unroll
            for (int it = 0; it < 2; ++it) {
                int u = tid + it*TPB;
                int r = u >> 5, seg = u & 31;
                size_t go = bbase + (size_t)r*256 + seg*8;
                uint32_t so = r*(B_STRIDE*2) + seg*16;
                cp16(st + OFF_BHI + so, g_wB_hi + go);
                cp16(st + OFF_BLO + so, g_wB_lo + go);
            }
        }
        cp_commit();
    };

    // warp tile: 32 tokens x 64 channels; 4 warps (M) x 4 warps (N)
    const int wm = wid & 3;
    const int wn = wid >> 2;

    wmma::fragment<wmma::accumulator, 16, 16, 16, float> acc[2][4];
    #pragma unroll
    for (int i = 0; i < 2; ++i)
        #pragma unroll
        for (int j = 0; j < 4; ++j)
            wmma::fill_fragment(acc[i][j], 0.f);

    load_chunk(0);
    load_chunk(1);

    for (int c = 0; c < NCHUNK; ++c) {
        if (c < NCHUNK - 1) cp_wait<1>(); else cp_wait<0>();
        __syncthreads();
        const char* stg = smem + (size_t)(c % 3) * STAGE_BYTES;
        const __nv_bfloat16* Ah = (const __nv_bfloat16*)(stg);
        const __nv_bfloat16* Al = (const __nv_bfloat16*)(stg + OFF_ALO);
        const __nv_bfloat16* Bh = (const __nv_bfloat16*)(stg + OFF_BHI);
        const __nv_bfloat16* Bl = (const __nv_bfloat16*)(stg + OFF_BLO);
        #pragma unroll
        for (int ks = 0; ks < 2; ++ks) {
            wmma::fragment<wmma::matrix_a, 16, 16, 16, __nv_bfloat16, wmma::row_major> ah[2], al[2];
            #pragma unroll
            for (int i = 0; i < 2; ++i) {
                wmma::load_matrix_sync(ah[i], Ah + (wm*32 + i*16)*A_STRIDE + ks*16, A_STRIDE);
                wmma::load_matrix_sync(al[i], Al + (wm*32 + i*16)*A_STRIDE + ks*16, A_STRIDE);
            }
            #pragma unroll
            for (int j = 0; j < 4; ++j) {
                wmma::fragment<wmma::matrix_b, 16, 16, 16, __nv_bfloat16, wmma::row_major> bh, bl;
                wmma::load_matrix_sync(bh, Bh + (ks*16)*B_STRIDE + wn*64 + j*16, B_STRIDE);
                wmma::load_matrix_sync(bl, Bl + (ks*16)*B_STRIDE + wn*64 + j*16, B_STRIDE);
                #pragma unroll
                for (int i = 0; i < 2; ++i) {
                    wmma::mma_sync(acc[i][j], ah[i], bh, acc[i][j]);
                    wmma::mma_sync(acc[i][j], ah[i], bl, acc[i][j]);
                    wmma::mma_sync(acc[i][j], al[i], bh, acc[i][j]);
                }
            }
        }
        // issue loads for chunk c+2 AFTER compute; buffer (c+2)%3 was consumed at
        // iteration c-1 (all threads passed this iteration's barrier since then).
        if (c + 2 < NCHUNK) load_chunk(c + 2);
    }

    // store accumulators to smem (C overlaps stage buffers; MMA phase done)
    __syncthreads();
    #pragma unroll
    for (int i = 0; i < 2; ++i)
        #pragma unroll
        for (int j = 0; j < 4; ++j)
            wmma::store_matrix_sync(Cs + (size_t)(wm*32 + i*16)*C_STRIDE + wn*64 + j*16,
                                    acc[i][j], C_STRIDE, wmma::mem_row_major);
    __syncthreads();

    // epilogue: each warp handles 8 token rows
    #pragma unroll
    for (int rr = 0; rr < 8; ++rr) {
        const int row = wid*8 + rr;
        float v[8];
        float s = 0.f, ss = 0.f;
        #pragma unroll
        for (int j = 0; j < 8; ++j) {
            v[j] = Cs[(size_t)row*C_STRIDE + lane + j*32] + par[lane + j*32];
            s  += v[j];
            ss += v[j]*v[j];
        }
        #pragma unroll
        for (int o = 16; o > 0; o >>= 1) {
            s  += __shfl_xor_sync(0xffffffffu, s,  o);
            ss += __shfl_xor_sync(0xffffffffu, ss, o);
        }
        const float mu = s * (1.f/FF);
        const float rs = rsqrtf(ss * (1.f/FF) - mu*mu + EPSF);

        if (!STAGE) {
            size_t ro = ((size_t)(b*(TT+2) + t0 + 1 + row))*FF;
            #pragma unroll
            for (int j = 0; j < 8; ++j) {
                int cch = lane + j*32;
                float w = fmaf((v[j] - mu)*rs, par[256 + cch], par[512 + cch]);
                w = fmaxf(w, 0.f);
                __nv_bfloat16 hi = __float2bfloat16(w);
                g_h1_hi[ro + cch] = hi;
                g_h1_lo[ro + cch] = __float2bfloat16(w - __bfloat162float(hi));
            }
        } else {
            float dot = 0.f;
            #pragma unroll
            for (int j = 0; j < 8; ++j) {
                int cch = lane + j*32;
                float w = fmaf((v[j] - mu)*rs, par[256 + cch], par[512 + cch]);
                dot = fmaf(fmaxf(w, 0.f), par[768 + cch], dot);
            }
            #pragma unroll
            for (int o = 16; o > 0; o >>= 1)
                dot += __shfl_xor_sync(0xffffffffu, dot, o);
            if (lane == 0)
                dur_out[b*TT + t0 + row] = fmaxf(dot + lin_b[0], 0.f);
        }
    }
}

// ---------------- cumsum + searchsorted ----------------
__global__ void cum_idx(const int* __restrict__ target) {
    __shared__ int cs[TT];
    __shared__ int wsum[16];
    const int b = blockIdx.x, t = threadIdx.x;
    const int wid = t >> 5, lid = t & 31;
    int sc = target[b*TT + t];
    #pragma unroll
    for (int o = 1; o < 32; o <<= 1) {
        int n = __shfl_up_sync(0xffffffffu, sc, o);
        if (lid >= o) sc += n;
    }
    if (lid == 31) wsum[wid] = sc;
    __syncthreads();
    if (wid == 0 && lid < 16) {
        int w = wsum[lid];
        #pragma unroll
        for (int o = 1; o < 16; o <<= 1) {
            int n = __shfl_up_sync(0xffffu, w, o);
            if (lid >= o) w += n;
        }
        wsum[lid] = w;
    }
    __syncthreads();
    cs[t] = sc + (wid ? wsum[wid-1] : 0);
    __syncthreads();
    const int total = cs[TT-1];
    for (int to = t; to < MEL; to += TT) {
        int lo = 0, hi = TT;
        while (lo < hi) {
            int mid = (lo + hi) >> 1;
            if (cs[mid] <= to) lo = mid + 1; else hi = mid;
        }
        g_idx[b*MEL + to] = (to < total) ? min(lo, TT-1) : -1;
    }
}

// ---------------- gather ----------------
__global__ void gather_k(const float* __restrict__ x, float* __restrict__ out) {
    const long long i  = (long long)blockIdx.x * blockDim.x + threadIdx.x;
    const long long N4 = (long long)BB * MEL * (DD/4);
    if (i >= N4) return;
    const int c4 = (int)(i & 63);
    const long long row = i >> 6;
    const int b   = (int)(row / MEL);
    const int idx = g_idx[row];
    float4 v = make_float4(0.f, 0.f, 0.f, 0.f);
    if (idx >= 0)
        v = reinterpret_cast<const float4*>(x)[((long long)b*TT + idx)*(DD/4) + c4];
    reinterpret_cast<float4*>(out)[i] = v;
}

// ---------------- launch ----------------
extern "C" void kernel_launch(void* const* d_in, const int* in_sizes, int n_in,
                              void* d_out, int out_size) {
    int base = 2;
    if (n_in >= 13 && in_sizes[2] == 1) base = 3;

    const float* x      = (const float*)d_in[0];
    const int*   target = (const int*)  d_in[1];
    const float* c1w = (const float*)d_in[base + 0];
    const float* c1b = (const float*)d_in[base + 1];
    const float* l1g = (const float*)d_in[base + 2];
    const float* l1b = (const float*)d_in[base + 3];
    const float* c2w = (const float*)d_in[base + 4];
    const float* c2b = (const float*)d_in[base + 5];
    const float* l2g = (const float*)d_in[base + 6];
    const float* l2b = (const float*)d_in[base + 7];
    const float* lw  = (const float*)d_in[base + 8];
    const float* lb  = (const float*)d_in[base + 9];

    float* out = (float*)d_out;
    float* dur = out + (size_t)BB * MEL * DD;

    cudaFuncSetAttribute(conv_wmma<0>, cudaFuncAttributeMaxDynamicSharedMemorySize, SMEM_BYTES);
    cudaFuncSetAttribute(conv_wmma<1>, cudaFuncAttributeMaxDynamicSharedMemorySize, SMEM_BYTES);

    prep_x<<<512, 256>>>(x);
    prep_w<<<512, 256>>>(c1w, c2w);
    cum_idx<<<BB, TT>>>(target);

    const long long N4 = (long long)BB * MEL * (DD/4);
    gather_k<<<(int)((N4 + 255)/256), 256>>>(x, out);

    conv_wmma<0><<<BB*NTILES, TPB, SMEM_BYTES>>>(c1b, l1g, l1b, lw, lb, nullptr);
    conv_wmma<1><<<BB*NTILES, TPB, SMEM_BYTES>>>(c2b, l2g, l2b, lw, lb, dur);
}

// round 7
// speedup vs baseline: 2.3582x; 1.5127x over previous
#include <cuda_runtime.h>
#include <cuda_fp16.h>
#include <mma.h>
#include <cstdint>

using namespace nvcuda;

#define BB   32
#define TT   512
#define DD   256
#define FF   256
#define MEL  2304
#define EPSF 1e-5f
#define WSCALE 256.f
#define WSCALE2 65536.f      // WSCALE^2, used to scale eps exactly

#define TPB    512      // 16 warps
#define NCHUNK 24       // K=768 in chunks of 32
#define MTILE  128      // tokens per block
#define NTILES 4        // tiles per batch -> 128 blocks total

// ---------------- device scratch ----------------
__device__ __align__(128) __half g_xpad [(size_t)BB*(TT+2)*DD];   // fp16 x (padded)
__device__ __align__(128) __half g_h1   [(size_t)BB*(TT+2)*FF];   // fp16 h1 (padded)
__device__ __align__(128) __half g_wH   [2*768*256];              // [stage][kcol][f], w*256 hi
__device__ __align__(128) __half g_wL   [2*768*256];              // residual lo
__device__ int g_idx[BB*MEL];

// ---------------- smem layout (bytes) ----------------
// 3 stages x 44032:
//   A    128x40 fp16 @ +0      (10240)
//   B_hi 32x264 fp16 @ +10240  (16896)
//   B_lo 32x264 fp16 @ +27136  (16896)
// C 128x264 f32 @0 (135168, overlaps stages after MMA phase)
// par 1024 f32 @135168
#define STAGE_BYTES 44032
#define OFF_BHI  10240
#define OFF_BLO  27136
#define OFF_PAR  135168
#define SMEM_BYTES 139264
#define A_STRIDE 40
#define B_STRIDE 264
#define C_STRIDE 264

__device__ __forceinline__ uint32_t smem_u32(const void* p) {
    uint32_t a;
    asm("{ .reg .u64 t; cvta.to.shared.u64 t, %1; cvt.u32.u64 %0, t; }" : "=r"(a) : "l"(p));
    return a;
}
__device__ __forceinline__ void cp16(uint32_t dst, const void* src) {
    asm volatile("cp.async.cg.shared.global [%0], [%1], 16;" :: "r"(dst), "l"(src));
}
__device__ __forceinline__ void cp_commit() { asm volatile("cp.async.commit_group;" ::: "memory"); }
template<int N> __device__ __forceinline__ void cp_wait() { asm volatile("cp.async.wait_group %0;" :: "n"(N) : "memory"); }

// ---------------- prep ----------------
__global__ void prep_x(const float* __restrict__ x) {
    const int NTOT = BB*(TT+2)*DD;
    for (int i = blockIdx.x*blockDim.x + threadIdx.x; i < NTOT; i += gridDim.x*blockDim.x) {
        int d   = i & (DD-1);
        int row = i >> 8;
        int t   = row % (TT+2);
        int b   = row / (TT+2);
        float v = (t == 0 || t == TT+1) ? 0.f : x[((size_t)(b*TT + t - 1))*DD + d];
        g_xpad[i] = __float2half(v);
    }
}
__global__ void prep_w(const float* __restrict__ w1, const float* __restrict__ w2) {
    const int NW = 2*768*256;
    for (int i = blockIdx.x*blockDim.x + threadIdx.x; i < NW; i += gridDim.x*blockDim.x) {
        int f    = i & 255;
        int rest = i >> 8;
        int kcol = rest % 768;
        int st   = rest / 768;
        int k    = kcol >> 8;
        int d    = kcol & 255;
        const float* w = st ? w2 : w1;
        float v = w[(f*DD + d)*3 + k] * WSCALE;
        __half hi = __float2half(v);
        g_wH[i] = hi;
        g_wL[i] = __float2half(v - __half2float(hi));
    }
    // zero padded edge rows of h1
    for (int i = blockIdx.x*blockDim.x + threadIdx.x; i < 2*BB*FF; i += gridDim.x*blockDim.x) {
        int d = i & (FF-1);
        int r = i >> 8;
        int b = r >> 1;
        int t = (r & 1) ? (TT+1) : 0;
        g_h1[((size_t)(b*(TT+2) + t))*FF + d] = __float2half(0.f);
    }
}

// ---------------- fused conv(K=3) fp16 2-MMA GEMM + bias + LN + ReLU (+linear) ----------------
// Weights (and bias) pre-scaled by WSCALE; LN uses eps*WSCALE^2 => exactly equivalent to reference.
template<int STAGE>
__global__ __launch_bounds__(TPB, 1)
void conv_wmma(const float* __restrict__ bias,
               const float* __restrict__ gamma,
               const float* __restrict__ beta,
               const float* __restrict__ lin_w,
               const float* __restrict__ lin_b,
               float* __restrict__ dur_out) {
    extern __shared__ char smem[];
    const uint32_t sbase = smem_u32(smem);
    const int tid  = threadIdx.x;
    const int wid  = tid >> 5;
    const int lane = tid & 31;
    const int b    = blockIdx.x >> 2;
    const int t0   = (blockIdx.x & 3) * MTILE;

    const __half* __restrict__ srcA = STAGE ? g_h1 : g_xpad;
    float* Cs  = (float*)smem;
    float* par = (float*)(smem + OFF_PAR);

    if (tid < 256) {
        par[tid]       = bias [tid] * WSCALE;   // scaled like the weights
        par[256 + tid] = gamma[tid];
        par[512 + tid] = beta [tid];
        par[768 + tid] = STAGE ? lin_w[tid] : 0.f;
    }

    auto load_chunk = [&](int c) {
        const uint32_t st = sbase + (uint32_t)(c % 3) * STAGE_BYTES;
        const int k   = c >> 3;
        const int d0  = (c & 7) * 32;
        // A: 128 rows x 32 fp16 cols = 4 x 16B segs per row -> 512 cp16
        {
            int r = tid >> 2, seg = tid & 3;
            size_t go = ((size_t)(b*(TT+2) + t0 + k + r))*DD + d0 + seg*8;
            cp16(st + r*(A_STRIDE*2) + seg*16, srcA + go);
        }
        // B: 32 rows x 256 fp16 cols = 32 x 16B segs per row -> 1024 cp16 each hi/lo
        {
            const size_t bbase = ((size_t)(STAGE*768 + c*32))*256;
            #pragma unroll
            for (int it = 0; it < 2; ++it) {
                int u = tid + it*TPB;
                int r = u >> 5, seg = u & 31;
                size_t go = bbase + (size_t)r*256 + seg*8;
                uint32_t so = r*(B_STRIDE*2) + seg*16;
                cp16(st + OFF_BHI + so, g_wH + go);
                cp16(st + OFF_BLO + so, g_wL + go);
            }
        }
        cp_commit();
    };

    // warp tile: 32 tokens x 64 channels; 4 warps (M) x 4 warps (N)
    const int wm = wid & 3;
    const int wn = wid >> 2;

    wmma::fragment<wmma::accumulator, 16, 16, 16, float> acc[2][4];
    #pragma unroll
    for (int i = 0; i < 2; ++i)
        #pragma unroll
        for (int j = 0; j < 4; ++j)
            wmma::fill_fragment(acc[i][j], 0.f);

    load_chunk(0);
    load_chunk(1);

    for (int c = 0; c < NCHUNK; ++c) {
        if (c < NCHUNK - 1) cp_wait<1>(); else cp_wait<0>();
        __syncthreads();
        const char* stg = smem + (size_t)(c % 3) * STAGE_BYTES;
        const __half* As = (const __half*)(stg);
        const __half* Bh = (const __half*)(stg + OFF_BHI);
        const __half* Bl = (const __half*)(stg + OFF_BLO);
        #pragma unroll
        for (int ks = 0; ks < 2; ++ks) {
            wmma::fragment<wmma::matrix_a, 16, 16, 16, __half, wmma::row_major> af[2];
            #pragma unroll
            for (int i = 0; i < 2; ++i)
                wmma::load_matrix_sync(af[i], As + (wm*32 + i*16)*A_STRIDE + ks*16, A_STRIDE);
            #pragma unroll
            for (int j = 0; j < 4; ++j) {
                wmma::fragment<wmma::matrix_b, 16, 16, 16, __half, wmma::row_major> bh, bl;
                wmma::load_matrix_sync(bh, Bh + (ks*16)*B_STRIDE + wn*64 + j*16, B_STRIDE);
                wmma::load_matrix_sync(bl, Bl + (ks*16)*B_STRIDE + wn*64 + j*16, B_STRIDE);
                #pragma unroll
                for (int i = 0; i < 2; ++i) {
                    wmma::mma_sync(acc[i][j], af[i], bh, acc[i][j]);
                    wmma::mma_sync(acc[i][j], af[i], bl, acc[i][j]);
                }
            }
        }
        // loads for chunk c+2 AFTER compute; buffer (c+2)%3 was consumed at iter c-1.
        if (c + 2 < NCHUNK) load_chunk(c + 2);
    }

    // store accumulators to smem (C overlaps stage buffers; MMA phase done)
    __syncthreads();
    #pragma unroll
    for (int i = 0; i < 2; ++i)
        #pragma unroll
        for (int j = 0; j < 4; ++j)
            wmma::store_matrix_sync(Cs + (size_t)(wm*32 + i*16)*C_STRIDE + wn*64 + j*16,
                                    acc[i][j], C_STRIDE, wmma::mem_row_major);
    __syncthreads();

    // epilogue: each warp handles 8 token rows. Values are WSCALE x reference;
    // LN with eps*WSCALE^2 cancels the scale exactly.
    #pragma unroll
    for (int rr = 0; rr < 8; ++rr) {
        const int row = wid*8 + rr;
        float v[8];
        float s = 0.f, ss = 0.f;
        #pragma unroll
        for (int j = 0; j < 8; ++j) {
            v[j] = Cs[(size_t)row*C_STRIDE + lane + j*32] + par[lane + j*32];
            s  += v[j];
            ss += v[j]*v[j];
        }
        #pragma unroll
        for (int o = 16; o > 0; o >>= 1) {
            s  += __shfl_xor_sync(0xffffffffu, s,  o);
            ss += __shfl_xor_sync(0xffffffffu, ss, o);
        }
        const float mu = s * (1.f/FF);
        const float rs = rsqrtf(ss * (1.f/FF) - mu*mu + EPSF*WSCALE2);

        if (!STAGE) {
            size_t ro = ((size_t)(b*(TT+2) + t0 + 1 + row))*FF;
            #pragma unroll
            for (int j = 0; j < 8; ++j) {
                int cch = lane + j*32;
                float w = fmaf((v[j] - mu)*rs, par[256 + cch], par[512 + cch]);
                g_h1[ro + cch] = __float2half(fmaxf(w, 0.f));
            }
        } else {
            float dot = 0.f;
            #pragma unroll
            for (int j = 0; j < 8; ++j) {
                int cch = lane + j*32;
                float w = fmaf((v[j] - mu)*rs, par[256 + cch], par[512 + cch]);
                dot = fmaf(fmaxf(w, 0.f), par[768 + cch], dot);
            }
            #pragma unroll
            for (int o = 16; o > 0; o >>= 1)
                dot += __shfl_xor_sync(0xffffffffu, dot, o);
            if (lane == 0)
                dur_out[b*TT + t0 + row] = fmaxf(dot + lin_b[0], 0.f);
        }
    }
}

// ---------------- cumsum + searchsorted ----------------
__global__ void cum_idx(const int* __restrict__ target) {
    __shared__ int cs[TT];
    __shared__ int wsum[16];
    const int b = blockIdx.x, t = threadIdx.x;
    const int wid = t >> 5, lid = t & 31;
    int sc = target[b*TT + t];
    #pragma unroll
    for (int o = 1; o < 32; o <<= 1) {
        int n = __shfl_up_sync(0xffffffffu, sc, o);
        if (lid >= o) sc += n;
    }
    if (lid == 31) wsum[wid] = sc;
    __syncthreads();
    if (wid == 0 && lid < 16) {
        int w = wsum[lid];
        #pragma unroll
        for (int o = 1; o < 16; o <<= 1) {
            int n = __shfl_up_sync(0xffffu, w, o);
            if (lid >= o) w += n;
        }
        wsum[lid] = w;
    }
    __syncthreads();
    cs[t] = sc + (wid ? wsum[wid-1] : 0);
    __syncthreads();
    const int total = cs[TT-1];
    for (int to = t; to < MEL; to += TT) {
        int lo = 0, hi = TT;
        while (lo < hi) {
            int mid = (lo + hi) >> 1;
            if (cs[mid] <= to) lo = mid + 1; else hi = mid;
        }
        g_idx[b*MEL + to] = (to < total) ? min(lo, TT-1) : -1;
    }
}

// ---------------- gather ----------------
__global__ void gather_k(const float* __restrict__ x, float* __restrict__ out) {
    const long long i  = (long long)blockIdx.x * blockDim.x + threadIdx.x;
    const long long N4 = (long long)BB * MEL * (DD/4);
    if (i >= N4) return;
    const int c4 = (int)(i & 63);
    const long long row = i >> 6;
    const int b   = (int)(row / MEL);
    const int idx = g_idx[row];
    float4 v = make_float4(0.f, 0.f, 0.f, 0.f);
    if (idx >= 0)
        v = reinterpret_cast<const float4*>(x)[((long long)b*TT + idx)*(DD/4) + c4];
    reinterpret_cast<float4*>(out)[i] = v;
}

// ---------------- launch ----------------
extern "C" void kernel_launch(void* const* d_in, const int* in_sizes, int n_in,
                              void* d_out, int out_size) {
    int base = 2;
    if (n_in >= 13 && in_sizes[2] == 1) base = 3;

    const float* x      = (const float*)d_in[0];
    const int*   target = (const int*)  d_in[1];
    const float* c1w = (const float*)d_in[base + 0];
    const float* c1b = (const float*)d_in[base + 1];
    const float* l1g = (const float*)d_in[base + 2];
    const float* l1b = (const float*)d_in[base + 3];
    const float* c2w = (const float*)d_in[base + 4];
    const float* c2b = (const float*)d_in[base + 5];
    const float* l2g = (const float*)d_in[base + 6];
    const float* l2b = (const float*)d_in[base + 7];
    const float* lw  = (const float*)d_in[base + 8];
    const float* lb  = (const float*)d_in[base + 9];

    float* out = (float*)d_out;
    float* dur = out + (size_t)BB * MEL * DD;

    cudaFuncSetAttribute(conv_wmma<0>, cudaFuncAttributeMaxDynamicSharedMemorySize, SMEM_BYTES);
    cudaFuncSetAttribute(conv_wmma<1>, cudaFuncAttributeMaxDynamicSharedMemorySize, SMEM_BYTES);

    prep_x<<<512, 256>>>(x);
    prep_w<<<512, 256>>>(c1w, c2w);
    cum_idx<<<BB, TT>>>(target);

    const long long N4 = (long long)BB * MEL * (DD/4);
    gather_k<<<(int)((N4 + 255)/256), 256>>>(x, out);

    conv_wmma<0><<<BB*NTILES, TPB, SMEM_BYTES>>>(c1b, l1g, l1b, lw, lb, nullptr);
    conv_wmma<1><<<BB*NTILES, TPB, SMEM_BYTES>>>(c2b, l2g, l2b, lw, lb, dur);
}

// round 8
// speedup vs baseline: 3.2915x; 1.3957x over previous
#include <cuda_runtime.h>
#include <cuda_fp16.h>
#include <mma.h>
#include <cstdint>

using namespace nvcuda;

#define BB   32
#define TT   512
#define DD   256
#define FF   256
#define MEL  2304
#define EPSF 1e-5f

#define TPB    512      // 16 warps
#define NCHUNK 24       // K=768 in chunks of 32
#define MTILE  128      // tokens per block
#define NTILES 4        // tiles per batch -> 128 blocks total

// ---------------- device scratch ----------------
__device__ __align__(128) __half g_xpad [(size_t)BB*(TT+2)*DD];   // fp16 x (padded)
__device__ __align__(128) __half g_h1   [(size_t)BB*(TT+2)*FF];   // fp16 h1 (padded)
__device__ __align__(128) __half g_wB   [2*768*256];              // [stage][kcol][f] fp16
__device__ int g_idx[BB*MEL];

// ---------------- smem layout (bytes) ----------------
// 3 stages x 27136:
//   A 128x40 fp16 @ +0      (10240)
//   B 32x264 fp16 @ +10240  (16896)
// C 128x264 f32 @0 (135168, overlaps stages after MMA phase)
// par 1024 f32 @135168
#define STAGE_BYTES 27136
#define OFF_B    10240
#define OFF_PAR  135168
#define SMEM_BYTES 139264
#define A_STRIDE 40
#define B_STRIDE 264
#define C_STRIDE 264

__device__ __forceinline__ uint32_t smem_u32(const void* p) {
    uint32_t a;
    asm("{ .reg .u64 t; cvta.to.shared.u64 t, %1; cvt.u32.u64 %0, t; }" : "=r"(a) : "l"(p));
    return a;
}
__device__ __forceinline__ void cp16(uint32_t dst, const void* src) {
    asm volatile("cp.async.cg.shared.global [%0], [%1], 16;" :: "r"(dst), "l"(src));
}
__device__ __forceinline__ void cp_commit() { asm volatile("cp.async.commit_group;" ::: "memory"); }
template<int N> __device__ __forceinline__ void cp_wait() { asm volatile("cp.async.wait_group %0;" :: "n"(N) : "memory"); }

// ---------------- prep ----------------
__global__ void prep_x(const float* __restrict__ x) {
    const int NTOT = BB*(TT+2)*DD;
    for (int i = blockIdx.x*blockDim.x + threadIdx.x; i < NTOT; i += gridDim.x*blockDim.x) {
        int d   = i & (DD-1);
        int row = i >> 8;
        int t   = row % (TT+2);
        int b   = row / (TT+2);
        float v = (t == 0 || t == TT+1) ? 0.f : x[((size_t)(b*TT + t - 1))*DD + d];
        g_xpad[i] = __float2half(v);
    }
}
__global__ void prep_w(const float* __restrict__ w1, const float* __restrict__ w2) {
    const int NW = 2*768*256;
    for (int i = blockIdx.x*blockDim.x + threadIdx.x; i < NW; i += gridDim.x*blockDim.x) {
        int f    = i & 255;
        int rest = i >> 8;
        int kcol = rest % 768;
        int st   = rest / 768;
        int k    = kcol >> 8;
        int d    = kcol & 255;
        const float* w = st ? w2 : w1;
        g_wB[i] = __float2half(w[(f*DD + d)*3 + k]);
    }
    // zero padded edge rows of h1
    for (int i = blockIdx.x*blockDim.x + threadIdx.x; i < 2*BB*FF; i += gridDim.x*blockDim.x) {
        int d = i & (FF-1);
        int r = i >> 8;
        int b = r >> 1;
        int t = (r & 1) ? (TT+1) : 0;
        g_h1[((size_t)(b*(TT+2) + t))*FF + d] = __float2half(0.f);
    }
}

// ---------------- fused conv(K=3) fp16 WMMA GEMM + bias + LN + ReLU (+linear) ----------------
template<int STAGE>
__global__ __launch_bounds__(TPB, 1)
void conv_wmma(const float* __restrict__ bias,
               const float* __restrict__ gamma,
               const float* __restrict__ beta,
               const float* __restrict__ lin_w,
               const float* __restrict__ lin_b,
               float* __restrict__ dur_out) {
    extern __shared__ char smem[];
    const uint32_t sbase = smem_u32(smem);
    const int tid  = threadIdx.x;
    const int wid  = tid >> 5;
    const int lane = tid & 31;
    const int b    = blockIdx.x >> 2;
    const int t0   = (blockIdx.x & 3) * MTILE;

    const __half* __restrict__ srcA = STAGE ? g_h1 : g_xpad;
    float* Cs  = (float*)smem;
    float* par = (float*)(smem + OFF_PAR);

    if (tid < 256) {
        par[tid]       = bias [tid];
        par[256 + tid] = gamma[tid];
        par[512 + tid] = beta [tid];
        par[768 + tid] = STAGE ? lin_w[tid] : 0.f;
    }

    auto load_chunk = [&](int c) {
        const uint32_t st = sbase + (uint32_t)(c % 3) * STAGE_BYTES;
        const int k   = c >> 3;
        const int d0  = (c & 7) * 32;
        // A: 128 rows x 32 fp16 cols = 4 x 16B segs per row -> 512 cp16
        {
            int r = tid >> 2, seg = tid & 3;
            size_t go = ((size_t)(b*(TT+2) + t0 + k + r))*DD + d0 + seg*8;
            cp16(st + r*(A_STRIDE*2) + seg*16, srcA + go);
        }
        // B: 32 rows x 256 fp16 cols = 32 x 16B segs per row -> 1024 cp16
        {
            const size_t bbase = ((size_t)(STAGE*768 + c*32))*256;
            #pragma unroll
            for (int it = 0; it < 2; ++it) {
                int u = tid + it*TPB;
                int r = u >> 5, seg = u & 31;
                cp16(st + OFF_B + r*(B_STRIDE*2) + seg*16, g_wB + bbase + (size_t)r*256 + seg*8);
            }
        }
        cp_commit();
    };

    // warp tile: 32 tokens x 64 channels; 4 warps (M) x 4 warps (N)
    const int wm = wid & 3;
    const int wn = wid >> 2;

    wmma::fragment<wmma::accumulator, 16, 16, 16, float> acc[2][4];
    #pragma unroll
    for (int i = 0; i < 2; ++i)
        #pragma unroll
        for (int j = 0; j < 4; ++j)
            wmma::fill_fragment(acc[i][j], 0.f);

    load_chunk(0);
    load_chunk(1);

    for (int c = 0; c < NCHUNK; ++c) {
        if (c < NCHUNK - 1) cp_wait<1>(); else cp_wait<0>();
        __syncthreads();
        const char* stg = smem + (size_t)(c % 3) * STAGE_BYTES;
        const __half* As = (const __half*)(stg);
        const __half* Bs = (const __half*)(stg + OFF_B);
        #pragma unroll
        for (int ks = 0; ks < 2; ++ks) {
            wmma::fragment<wmma::matrix_a, 16, 16, 16, __half, wmma::row_major> af[2];
            #pragma unroll
            for (int i = 0; i < 2; ++i)
                wmma::load_matrix_sync(af[i], As + (wm*32 + i*16)*A_STRIDE + ks*16, A_STRIDE);
            #pragma unroll
            for (int j = 0; j < 4; ++j) {
                wmma::fragment<wmma::matrix_b, 16, 16, 16, __half, wmma::row_major> bf;
                wmma::load_matrix_sync(bf, Bs + (ks*16)*B_STRIDE + wn*64 + j*16, B_STRIDE);
                #pragma unroll
                for (int i = 0; i < 2; ++i)
                    wmma::mma_sync(acc[i][j], af[i], bf, acc[i][j]);
            }
        }
        // loads for chunk c+2 AFTER compute; buffer (c+2)%3 was consumed at iter c-1.
        if (c + 2 < NCHUNK) load_chunk(c + 2);
    }

    // store accumulators to smem (C overlaps stage buffers; MMA phase done)
    __syncthreads();
    #pragma unroll
    for (int i = 0; i < 2; ++i)
        #pragma unroll
        for (int j = 0; j < 4; ++j)
            wmma::store_matrix_sync(Cs + (size_t)(wm*32 + i*16)*C_STRIDE + wn*64 + j*16,
                                    acc[i][j], C_STRIDE, wmma::mem_row_major);
    __syncthreads();

    // epilogue: each warp handles 8 token rows
    #pragma unroll
    for (int rr = 0; rr < 8; ++rr) {
        const int row = wid*8 + rr;
        float v[8];
        float s = 0.f, ss = 0.f;
        #pragma unroll
        for (int j = 0; j < 8; ++j) {
            v[j] = Cs[(size_t)row*C_STRIDE + lane + j*32] + par[lane + j*32];
            s  += v[j];
            ss += v[j]*v[j];
        }
        #pragma unroll
        for (int o = 16; o > 0; o >>= 1) {
            s  += __shfl_xor_sync(0xffffffffu, s,  o);
            ss += __shfl_xor_sync(0xffffffffu, ss, o);
        }
        const float mu = s * (1.f/FF);
        const float rs = rsqrtf(ss * (1.f/FF) - mu*mu + EPSF);

        if (!STAGE) {
            size_t ro = ((size_t)(b*(TT+2) + t0 + 1 + row))*FF;
            #pragma unroll
            for (int j = 0; j < 8; ++j) {
                int cch = lane + j*32;
                float w = fmaf((v[j] - mu)*rs, par[256 + cch], par[512 + cch]);
                g_h1[ro + cch] = __float2half(fmaxf(w, 0.f));
            }
        } else {
            float dot = 0.f;
            #pragma unroll
            for (int j = 0; j < 8; ++j) {
                int cch = lane + j*32;
                float w = fmaf((v[j] - mu)*rs, par[256 + cch], par[512 + cch]);
                dot = fmaf(fmaxf(w, 0.f), par[768 + cch], dot);
            }
            #pragma unroll
            for (int o = 16; o > 0; o >>= 1)
                dot += __shfl_xor_sync(0xffffffffu, dot, o);
            if (lane == 0)
                dur_out[b*TT + t0 + row] = fmaxf(dot + lin_b[0], 0.f);
        }
    }
}

// ---------------- cumsum + searchsorted ----------------
__global__ void cum_idx(const int* __restrict__ target) {
    __shared__ int cs[TT];
    __shared__ int wsum[16];
    const int b = blockIdx.x, t = threadIdx.x;
    const int wid = t >> 5, lid = t & 31;
    int sc = target[b*TT + t];
    #pragma unroll
    for (int o = 1; o < 32; o <<= 1) {
        int n = __shfl_up_sync(0xffffffffu, sc, o);
        if (lid >= o) sc += n;
    }
    if (lid == 31) wsum[wid] = sc;
    __syncthreads();
    if (wid == 0 && lid < 16) {
        int w = wsum[lid];
        #pragma unroll
        for (int o = 1; o < 16; o <<= 1) {
            int n = __shfl_up_sync(0xffffu, w, o);
            if (lid >= o) w += n;
        }
        wsum[lid] = w;
    }
    __syncthreads();
    cs[t] = sc + (wid ? wsum[wid-1] : 0);
    __syncthreads();
    const int total = cs[TT-1];
    for (int to = t; to < MEL; to += TT) {
        int lo = 0, hi = TT;
        while (lo < hi) {
            int mid = (lo + hi) >> 1;
            if (cs[mid] <= to) lo = mid + 1; else hi = mid;
        }
        g_idx[b*MEL + to] = (to < total) ? min(lo, TT-1) : -1;
    }
}

// ---------------- gather: 2 float4 per thread, streaming stores ----------------
__device__ __forceinline__ void st_cs(float4* p, float4 v) {
    asm volatile("st.global.cs.v4.f32 [%0], {%1,%2,%3,%4};"
                 :: "l"(p), "f"(v.x), "f"(v.y), "f"(v.z), "f"(v.w) : "memory");
}
__global__ void gather_k(const float* __restrict__ x, float* __restrict__ out) {
    // each thread: 2 consecutive float4 in channel dim (32 B)
    const long long u  = (long long)blockIdx.x * blockDim.x + threadIdx.x;
    const long long N8 = (long long)BB * MEL * (DD/8);
    if (u >= N8) return;
    const int c8 = (int)(u & 31);                 // 32 chunks of 8 floats
    const long long row = u >> 5;                 // b*MEL + to
    const int b   = (int)(row / MEL);
    const int idx = __ldg(&g_idx[row]);
    float4 v0 = make_float4(0.f,0.f,0.f,0.f), v1 = v0;
    if (idx >= 0) {
        const float4* src = reinterpret_cast<const float4*>(x) + ((long long)b*TT + idx)*(DD/4) + c8*2;
        v0 = __ldg(src);
        v1 = __ldg(src + 1);
    }
    float4* dst = reinterpret_cast<float4*>(out) + row*(DD/4) + c8*2;
    st_cs(dst,     v0);
    st_cs(dst + 1, v1);
}

// ---------------- launch ----------------
extern "C" void kernel_launch(void* const* d_in, const int* in_sizes, int n_in,
                              void* d_out, int out_size) {
    int base = 2;
    if (n_in >= 13 && in_sizes[2] == 1) base = 3;

    const float* x      = (const float*)d_in[0];
    const int*   target = (const int*)  d_in[1];
    const float* c1w = (const float*)d_in[base + 0];
    const float* c1b = (const float*)d_in[base + 1];
    const float* l1g = (const float*)d_in[base + 2];
    const float* l1b = (const float*)d_in[base + 3];
    const float* c2w = (const float*)d_in[base + 4];
    const float* c2b = (const float*)d_in[base + 5];
    const float* l2g = (const float*)d_in[base + 6];
    const float* l2b = (const float*)d_in[base + 7];
    const float* lw  = (const float*)d_in[base + 8];
    const float* lb  = (const float*)d_in[base + 9];

    float* out = (float*)d_out;
    float* dur = out + (size_t)BB * MEL * DD;

    cudaFuncSetAttribute(conv_wmma<0>, cudaFuncAttributeMaxDynamicSharedMemorySize, SMEM_BYTES);
    cudaFuncSetAttribute(conv_wmma<1>, cudaFuncAttributeMaxDynamicSharedMemorySize, SMEM_BYTES);

    prep_x<<<512, 256>>>(x);
    prep_w<<<512, 256>>>(c1w, c2w);
    cum_idx<<<BB, TT>>>(target);

    const long long N8 = (long long)BB * MEL * (DD/8);
    gather_k<<<(int)((N8 + 255)/256), 256>>>(x, out);

    conv_wmma<0><<<BB*NTILES, TPB, SMEM_BYTES>>>(c1b, l1g, l1b, lw, lb, nullptr);
    conv_wmma<1><<<BB*NTILES, TPB, SMEM_BYTES>>>(c2b, l2g, l2b, lw, lb, dur);
}

// round 9
// speedup vs baseline: 3.5347x; 1.0739x over previous
#include <cuda_runtime.h>
#include <cuda_fp16.h>
#include <mma.h>
#include <cstdint>

using namespace nvcuda;

#define BB   32
#define TT   512
#define DD   256
#define FF   256
#define MEL  2304
#define EPSF 1e-5f

#define TPB    512      // 16 warps
#define NCHUNK 24       // K=768 in chunks of 32
#define MTILE  128      // tokens per block
#define NTILES 4        // tiles per batch -> 128 blocks total

// ---------------- device scratch ----------------
__device__ __align__(128) __half g_xpad [(size_t)BB*(TT+2)*DD];   // fp16 x (padded)
__device__ __align__(128) __half g_h1   [(size_t)BB*(TT+2)*FF];   // fp16 h1 (padded)
__device__ __align__(128) __half g_wB   [2*768*256];              // [stage][kcol][f] fp16
__device__ int g_idx[BB*MEL];

// ---------------- smem layout (bytes) ----------------
#define STAGE_BYTES 27136
#define OFF_B    10240
#define OFF_PAR  135168
#define SMEM_BYTES 139264
#define A_STRIDE 40
#define B_STRIDE 264
#define C_STRIDE 264

__device__ __forceinline__ uint32_t smem_u32(const void* p) {
    uint32_t a;
    asm("{ .reg .u64 t; cvta.to.shared.u64 t, %1; cvt.u32.u64 %0, t; }" : "=r"(a) : "l"(p));
    return a;
}
__device__ __forceinline__ void cp16(uint32_t dst, const void* src) {
    asm volatile("cp.async.cg.shared.global [%0], [%1], 16;" :: "r"(dst), "l"(src));
}
__device__ __forceinline__ void cp_commit() { asm volatile("cp.async.commit_group;" ::: "memory"); }
template<int N> __device__ __forceinline__ void cp_wait() { asm volatile("cp.async.wait_group %0;" :: "n"(N) : "memory"); }

// ---------------- prep ----------------
__global__ void prep_x(const float* __restrict__ x) {
    const int NTOT = BB*(TT+2)*DD;
    for (int i = blockIdx.x*blockDim.x + threadIdx.x; i < NTOT; i += gridDim.x*blockDim.x) {
        int d   = i & (DD-1);
        int row = i >> 8;
        int t   = row % (TT+2);
        int b   = row / (TT+2);
        float v = (t == 0 || t == TT+1) ? 0.f : x[((size_t)(b*TT + t - 1))*DD + d];
        g_xpad[i] = __float2half(v);
    }
}
__global__ void prep_w(const float* __restrict__ w1, const float* __restrict__ w2) {
    const int NW = 2*768*256;
    for (int i = blockIdx.x*blockDim.x + threadIdx.x; i < NW; i += gridDim.x*blockDim.x) {
        int f    = i & 255;
        int rest = i >> 8;
        int kcol = rest % 768;
        int st   = rest / 768;
        int k    = kcol >> 8;
        int d    = kcol & 255;
        const float* w = st ? w2 : w1;
        g_wB[i] = __float2half(w[(f*DD + d)*3 + k]);
    }
    // zero padded edge rows of h1
    for (int i = blockIdx.x*blockDim.x + threadIdx.x; i < 2*BB*FF; i += gridDim.x*blockDim.x) {
        int d = i & (FF-1);
        int r = i >> 8;
        int b = r >> 1;
        int t = (r & 1) ? (TT+1) : 0;
        g_h1[((size_t)(b*(TT+2) + t))*FF + d] = __float2half(0.f);
    }
}

// ---------------- fused conv(K=3) fp16 WMMA GEMM + bias + LN + ReLU (+linear) ----------------
template<int STAGE>
__global__ __launch_bounds__(TPB, 1)
void conv_wmma(const float* __restrict__ bias,
               const float* __restrict__ gamma,
               const float* __restrict__ beta,
               const float* __restrict__ lin_w,
               const float* __restrict__ lin_b,
               float* __restrict__ dur_out) {
    extern __shared__ char smem[];
    const uint32_t sbase = smem_u32(smem);
    const int tid  = threadIdx.x;
    const int wid  = tid >> 5;
    const int lane = tid & 31;
    const int b    = blockIdx.x >> 2;
    const int t0   = (blockIdx.x & 3) * MTILE;

    const __half* __restrict__ srcA = STAGE ? g_h1 : g_xpad;
    float* Cs  = (float*)smem;
    float* par = (float*)(smem + OFF_PAR);

    if (tid < 256) {
        par[tid]       = bias [tid];
        par[256 + tid] = gamma[tid];
        par[512 + tid] = beta [tid];
        par[768 + tid] = STAGE ? lin_w[tid] : 0.f;
    }

    auto load_chunk = [&](int c) {
        const uint32_t st = sbase + (uint32_t)(c % 3) * STAGE_BYTES;
        const int k   = c >> 3;
        const int d0  = (c & 7) * 32;
        {
            int r = tid >> 2, seg = tid & 3;
            size_t go = ((size_t)(b*(TT+2) + t0 + k + r))*DD + d0 + seg*8;
            cp16(st + r*(A_STRIDE*2) + seg*16, srcA + go);
        }
        {
            const size_t bbase = ((size_t)(STAGE*768 + c*32))*256;
            #pragma unroll
            for (int it = 0; it < 2; ++it) {
                int u = tid + it*TPB;
                int r = u >> 5, seg = u & 31;
                cp16(st + OFF_B + r*(B_STRIDE*2) + seg*16, g_wB + bbase + (size_t)r*256 + seg*8);
            }
        }
        cp_commit();
    };

    const int wm = wid & 3;
    const int wn = wid >> 2;

    wmma::fragment<wmma::accumulator, 16, 16, 16, float> acc[2][4];
    #pragma unroll
    for (int i = 0; i < 2; ++i)
        #pragma unroll
        for (int j = 0; j < 4; ++j)
            wmma::fill_fragment(acc[i][j], 0.f);

    load_chunk(0);
    load_chunk(1);

    for (int c = 0; c < NCHUNK; ++c) {
        if (c < NCHUNK - 1) cp_wait<1>(); else cp_wait<0>();
        __syncthreads();
        const char* stg = smem + (size_t)(c % 3) * STAGE_BYTES;
        const __half* As = (const __half*)(stg);
        const __half* Bs = (const __half*)(stg + OFF_B);
        #pragma unroll
        for (int ks = 0; ks < 2; ++ks) {
            wmma::fragment<wmma::matrix_a, 16, 16, 16, __half, wmma::row_major> af[2];
            #pragma unroll
            for (int i = 0; i < 2; ++i)
                wmma::load_matrix_sync(af[i], As + (wm*32 + i*16)*A_STRIDE + ks*16, A_STRIDE);
            #pragma unroll
            for (int j = 0; j < 4; ++j) {
                wmma::fragment<wmma::matrix_b, 16, 16, 16, __half, wmma::row_major> bf;
                wmma::load_matrix_sync(bf, Bs + (ks*16)*B_STRIDE + wn*64 + j*16, B_STRIDE);
                #pragma unroll
                for (int i = 0; i < 2; ++i)
                    wmma::mma_sync(acc[i][j], af[i], bf, acc[i][j]);
            }
        }
        if (c + 2 < NCHUNK) load_chunk(c + 2);
    }

    __syncthreads();
    #pragma unroll
    for (int i = 0; i < 2; ++i)
        #pragma unroll
        for (int j = 0; j < 4; ++j)
            wmma::store_matrix_sync(Cs + (size_t)(wm*32 + i*16)*C_STRIDE + wn*64 + j*16,
                                    acc[i][j], C_STRIDE, wmma::mem_row_major);
    __syncthreads();

    #pragma unroll
    for (int rr = 0; rr < 8; ++rr) {
        const int row = wid*8 + rr;
        float v[8];
        float s = 0.f, ss = 0.f;
        #pragma unroll
        for (int j = 0; j < 8; ++j) {
            v[j] = Cs[(size_t)row*C_STRIDE + lane + j*32] + par[lane + j*32];
            s  += v[j];
            ss += v[j]*v[j];
        }
        #pragma unroll
        for (int o = 16; o > 0; o >>= 1) {
            s  += __shfl_xor_sync(0xffffffffu, s,  o);
            ss += __shfl_xor_sync(0xffffffffu, ss, o);
        }
        const float mu = s * (1.f/FF);
        const float rs = rsqrtf(ss * (1.f/FF) - mu*mu + EPSF);

        if (!STAGE) {
            size_t ro = ((size_t)(b*(TT+2) + t0 + 1 + row))*FF;
            #pragma unroll
            for (int j = 0; j < 8; ++j) {
                int cch = lane + j*32;
                float w = fmaf((v[j] - mu)*rs, par[256 + cch], par[512 + cch]);
                g_h1[ro + cch] = __float2half(fmaxf(w, 0.f));
            }
        } else {
            float dot = 0.f;
            #pragma unroll
            for (int j = 0; j < 8; ++j) {
                int cch = lane + j*32;
                float w = fmaf((v[j] - mu)*rs, par[256 + cch], par[512 + cch]);
                dot = fmaf(fmaxf(w, 0.f), par[768 + cch], dot);
            }
            #pragma unroll
            for (int o = 16; o > 0; o >>= 1)
                dot += __shfl_xor_sync(0xffffffffu, dot, o);
            if (lane == 0)
                dur_out[b*TT + t0 + row] = fmaxf(dot + lin_b[0], 0.f);
        }
    }
}

// ---------------- cumsum + searchsorted ----------------
__global__ void cum_idx(const int* __restrict__ target) {
    __shared__ int cs[TT];
    __shared__ int wsum[16];
    const int b = blockIdx.x, t = threadIdx.x;
    const int wid = t >> 5, lid = t & 31;
    int sc = target[b*TT + t];
    #pragma unroll
    for (int o = 1; o < 32; o <<= 1) {
        int n = __shfl_up_sync(0xffffffffu, sc, o);
        if (lid >= o) sc += n;
    }
    if (lid == 31) wsum[wid] = sc;
    __syncthreads();
    if (wid == 0 && lid < 16) {
        int w = wsum[lid];
        #pragma unroll
        for (int o = 1; o < 16; o <<= 1) {
            int n = __shfl_up_sync(0xffffu, w, o);
            if (lid >= o) w += n;
        }
        wsum[lid] = w;
    }
    __syncthreads();
    cs[t] = sc + (wid ? wsum[wid-1] : 0);
    __syncthreads();
    const int total = cs[TT-1];
    for (int to = t; to < MEL; to += TT) {
        int lo = 0, hi = TT;
        while (lo < hi) {
            int mid = (lo + hi) >> 1;
            if (cs[mid] <= to) lo = mid + 1; else hi = mid;
        }
        g_idx[b*MEL + to] = (to < total) ? min(lo, TT-1) : -1;
    }
}

// ---------------- gather ----------------
__device__ __forceinline__ void st_cs(float4* p, float4 v) {
    asm volatile("st.global.cs.v4.f32 [%0], {%1,%2,%3,%4};"
                 :: "l"(p), "f"(v.x), "f"(v.y), "f"(v.z), "f"(v.w) : "memory");
}
__global__ void gather_k(const float* __restrict__ x, float* __restrict__ out) {
    const long long u  = (long long)blockIdx.x * blockDim.x + threadIdx.x;
    const long long N8 = (long long)BB * MEL * (DD/8);
    if (u >= N8) return;
    const int c8 = (int)(u & 31);
    const long long row = u >> 5;
    const int b   = (int)(row / MEL);
    const int idx = __ldg(&g_idx[row]);
    float4 v0 = make_float4(0.f,0.f,0.f,0.f), v1 = v0;
    if (idx >= 0) {
        const float4* src = reinterpret_cast<const float4*>(x) + ((long long)b*TT + idx)*(DD/4) + c8*2;
        v0 = __ldg(src);
        v1 = __ldg(src + 1);
    }
    float4* dst = reinterpret_cast<float4*>(out) + row*(DD/4) + c8*2;
    st_cs(dst,     v0);
    st_cs(dst + 1, v1);
}

// ---------------- launch: fork/join two independent chains ----------------
extern "C" void kernel_launch(void* const* d_in, const int* in_sizes, int n_in,
                              void* d_out, int out_size) {
    int base = 2;
    if (n_in >= 13 && in_sizes[2] == 1) base = 3;

    const float* x      = (const float*)d_in[0];
    const int*   target = (const int*)  d_in[1];
    const float* c1w = (const float*)d_in[base + 0];
    const float* c1b = (const float*)d_in[base + 1];
    const float* l1g = (const float*)d_in[base + 2];
    const float* l1b = (const float*)d_in[base + 3];
    const float* c2w = (const float*)d_in[base + 4];
    const float* c2b = (const float*)d_in[base + 5];
    const float* l2g = (const float*)d_in[base + 6];
    const float* l2b = (const float*)d_in[base + 7];
    const float* lw  = (const float*)d_in[base + 8];
    const float* lb  = (const float*)d_in[base + 9];

    float* out = (float*)d_out;
    float* dur = out + (size_t)BB * MEL * DD;

    cudaFuncSetAttribute(conv_wmma<0>, cudaFuncAttributeMaxDynamicSharedMemorySize, SMEM_BYTES);
    cudaFuncSetAttribute(conv_wmma<1>, cudaFuncAttributeMaxDynamicSharedMemorySize, SMEM_BYTES);

    const long long N8 = (long long)BB * MEL * (DD/8);
    const int gatherBlocks = (int)((N8 + 255)/256);

    // Try fork/join: chain B (cum_idx -> gather) on a second stream, overlapping
    // chain A (prep -> conv1 -> conv2) on the capture/default stream.
    cudaStream_t s2 = nullptr;
    cudaEvent_t eFork = nullptr, eJoin = nullptr;
    bool forked = (cudaStreamCreateWithFlags(&s2, cudaStreamNonBlocking) == cudaSuccess)
               && (cudaEventCreateWithFlags(&eFork, cudaEventDisableTiming) == cudaSuccess)
               && (cudaEventCreateWithFlags(&eJoin, cudaEventDisableTiming) == cudaSuccess);

    if (forked && cudaEventRecord(eFork, 0) == cudaSuccess
               && cudaStreamWaitEvent(s2, eFork, 0) == cudaSuccess) {
        // chain B on s2
        cum_idx<<<BB, TT, 0, s2>>>(target);
        gather_k<<<gatherBlocks, 256, 0, s2>>>(x, out);
        cudaEventRecord(eJoin, s2);

        // chain A on default stream
        prep_x<<<512, 256>>>(x);
        prep_w<<<512, 256>>>(c1w, c2w);
        conv_wmma<0><<<BB*NTILES, TPB, SMEM_BYTES>>>(c1b, l1g, l1b, lw, lb, nullptr);
        conv_wmma<1><<<BB*NTILES, TPB, SMEM_BYTES>>>(c2b, l2g, l2b, lw, lb, dur);

        cudaStreamWaitEvent(0, eJoin, 0);

        cudaEventDestroy(eFork);
        cudaEventDestroy(eJoin);
        cudaStreamDestroy(s2);
    } else {
        // fallback: sequential on default stream (identical device work)
        if (s2)    cudaStreamDestroy(s2);
        if (eFork) cudaEventDestroy(eFork);
        if (eJoin) cudaEventDestroy(eJoin);

        prep_x<<<512, 256>>>(x);
        prep_w<<<512, 256>>>(c1w, c2w);
        cum_idx<<<BB, TT>>>(target);
        gather_k<<<gatherBlocks, 256>>>(x, out);
        conv_wmma<0><<<BB*NTILES, TPB, SMEM_BYTES>>>(c1b, l1g, l1b, lw, lb, nullptr);
        conv_wmma<1><<<BB*NTILES, TPB, SMEM_BYTES>>>(c2b, l2g, l2b, lw, lb, dur);
    }
}

// round 10
// speedup vs baseline: 3.7024x; 1.0475x over previous
#include <cuda_runtime.h>
#include <cuda_fp16.h>
#include <mma.h>
#include <cstdint>

using namespace nvcuda;

#define BB   32
#define TT   512
#define DD   256
#define FF   256
#define MEL  2304
#define EPSF 1e-5f

#define TPB    512      // 16 warps
#define NCHUNK 24       // K=768 in chunks of 32
#define MTILE  128      // tokens per block
#define NTILES 4        // tiles per batch -> 128 blocks total

// ---------------- device scratch ----------------
__device__ __align__(128) __half g_xpad [(size_t)BB*(TT+2)*DD];   // fp16 x (padded)
__device__ __align__(128) __half g_h1   [(size_t)BB*(TT+2)*FF];   // fp16 h1 (padded)
__device__ __align__(128) __half g_wB   [2*768*256];              // [stage][kcol][f] fp16
__device__ int g_idx[BB*MEL];

// ---------------- conv smem layout (bytes) ----------------
#define STAGE_BYTES 27136
#define OFF_B    10240
#define OFF_PAR  135168
#define SMEM_BYTES 139264
#define A_STRIDE 40
#define B_STRIDE 264
#define C_STRIDE 264

__device__ __forceinline__ uint32_t smem_u32(const void* p) {
    uint32_t a;
    asm("{ .reg .u64 t; cvta.to.shared.u64 t, %1; cvt.u32.u64 %0, t; }" : "=r"(a) : "l"(p));
    return a;
}
__device__ __forceinline__ void cp16(uint32_t dst, const void* src) {
    asm volatile("cp.async.cg.shared.global [%0], [%1], 16;" :: "r"(dst), "l"(src));
}
__device__ __forceinline__ void cp_commit() { asm volatile("cp.async.commit_group;" ::: "memory"); }
template<int N> __device__ __forceinline__ void cp_wait() { asm volatile("cp.async.wait_group %0;" :: "n"(N) : "memory"); }

// ---------------- fused prep: cum_idx (32) | prep_w transpose (16) | prep_x (516) ----------------
#define PW_PITCH 778                      // halves; lane stride 389 words, gcd(389,32)=1
#define PREP_SMEM (32*PW_PITCH*2)         // 49792 B
#define NXBLK 516
#define NTOTX (BB*(TT+2)*DD)

__global__ __launch_bounds__(512)
void prep_fused(const float* __restrict__ x,
                const float* __restrict__ w1,
                const float* __restrict__ w2,
                const int*   __restrict__ target) {
    extern __shared__ char dsm[];
    const int j   = blockIdx.x;
    const int tid = threadIdx.x;
    const int wid = tid >> 5, lane = tid & 31;

    if (j < 32) {
        // ---- cumsum + searchsorted for batch j ----
        int* cs   = (int*)dsm;          // 512
        int* wsum = (int*)dsm + 512;    // 16
        const int b = j, t = tid;
        int sc = target[b*TT + t];
        #pragma unroll
        for (int o = 1; o < 32; o <<= 1) {
            int n = __shfl_up_sync(0xffffffffu, sc, o);
            if (lane >= o) sc += n;
        }
        if (lane == 31) wsum[wid] = sc;
        __syncthreads();
        if (wid == 0 && lane < 16) {
            int w = wsum[lane];
            #pragma unroll
            for (int o = 1; o < 16; o <<= 1) {
                int n = __shfl_up_sync(0xffffu, w, o);
                if (lane >= o) w += n;
            }
            wsum[lane] = w;
        }
        __syncthreads();
        cs[t] = sc + (wid ? wsum[wid-1] : 0);
        __syncthreads();
        const int total = cs[TT-1];
        for (int to = t; to < MEL; to += TT) {
            int lo = 0, hi = TT;
            while (lo < hi) {
                int mid = (lo + hi) >> 1;
                if (cs[mid] <= to) lo = mid + 1; else hi = mid;
            }
            g_idx[b*MEL + to] = (to < total) ? min(lo, TT-1) : -1;
        }
    } else if (j < 48) {
        // ---- prep_w: transpose 32 f-rows x 768 m-cols, coalesced both sides ----
        const int jj    = j - 32;
        const int stg   = jj >> 3;
        const int f0    = (jj & 7) * 32;
        const float* w  = stg ? w2 : w1;
        __half* S = (__half*)dsm;       // S[f_local][m], pitch PW_PITCH halves
        // load: rows f0..f0+31, 768 floats each (192 float4/row), coalesced
        #pragma unroll
        for (int it = 0; it < 12; ++it) {
            int u  = tid + it*512;       // 0..6143
            int r  = u / 192;
            int m  = (u % 192) * 4;
            float4 v = __ldg((const float4*)(w + (size_t)(f0 + r)*768 + m));
            __half* dst = S + r*PW_PITCH + m;
            dst[0] = __float2half(v.x);
            dst[1] = __float2half(v.y);
            dst[2] = __float2half(v.z);
            dst[3] = __float2half(v.w);
        }
        __syncthreads();
        // write: each warp 48 kcol-rows; 32 consecutive halves per row (64B, coalesced)
        for (int i = 0; i < 48; ++i) {
            int kcol = wid*48 + i;
            int k = kcol >> 8, d = kcol & 255;
            int m = d*3 + k;
            g_wB[((size_t)(stg*768 + kcol))*256 + f0 + lane] = S[lane*PW_PITCH + m];
        }
    } else {
        // ---- prep_x + h1 edge zero ----
        const int bb = j - 48;
        #pragma unroll
        for (int it = 0; it < 16; ++it) {
            int i = (bb*16 + it)*512 + tid;
            if (i < NTOTX) {
                int d   = i & (DD-1);
                int row = i >> 8;
                int t   = row % (TT+2);
                int b   = row / (TT+2);
                float v = (t == 0 || t == TT+1) ? 0.f : x[((size_t)(b*TT + t - 1))*DD + d];
                g_xpad[i] = __float2half(v);
            }
        }
        if (bb == 0) {
            #pragma unroll
            for (int it = 0; it < 32; ++it) {
                int i = it*512 + tid;       // 0..16383
                int d = i & (FF-1);
                int r = i >> 8;
                int b = r >> 1;
                int t = (r & 1) ? (TT+1) : 0;
                g_h1[((size_t)(b*(TT+2) + t))*FF + d] = __float2half(0.f);
            }
        }
    }
}

// ---------------- fused conv(K=3) fp16 WMMA GEMM + bias + LN + ReLU (+linear) ----------------
template<int STAGE>
__global__ __launch_bounds__(TPB, 1)
void conv_wmma(const float* __restrict__ bias,
               const float* __restrict__ gamma,
               const float* __restrict__ beta,
               const float* __restrict__ lin_w,
               const float* __restrict__ lin_b,
               float* __restrict__ dur_out) {
    extern __shared__ char smem[];
    const uint32_t sbase = smem_u32(smem);
    const int tid  = threadIdx.x;
    const int wid  = tid >> 5;
    const int lane = tid & 31;
    const int b    = blockIdx.x >> 2;
    const int t0   = (blockIdx.x & 3) * MTILE;

    const __half* __restrict__ srcA = STAGE ? g_h1 : g_xpad;
    float* Cs  = (float*)smem;
    float* par = (float*)(smem + OFF_PAR);

    if (tid < 256) {
        par[tid]       = bias [tid];
        par[256 + tid] = gamma[tid];
        par[512 + tid] = beta [tid];
        par[768 + tid] = STAGE ? lin_w[tid] : 0.f;
    }

    auto load_chunk = [&](int c) {
        const uint32_t st = sbase + (uint32_t)(c % 3) * STAGE_BYTES;
        const int k   = c >> 3;
        const int d0  = (c & 7) * 32;
        {
            int r = tid >> 2, seg = tid & 3;
            size_t go = ((size_t)(b*(TT+2) + t0 + k + r))*DD + d0 + seg*8;
            cp16(st + r*(A_STRIDE*2) + seg*16, srcA + go);
        }
        {
            const size_t bbase = ((size_t)(STAGE*768 + c*32))*256;
            #pragma unroll
            for (int it = 0; it < 2; ++it) {
                int u = tid + it*TPB;
                int r = u >> 5, seg = u & 31;
                cp16(st + OFF_B + r*(B_STRIDE*2) + seg*16, g_wB + bbase + (size_t)r*256 + seg*8);
            }
        }
        cp_commit();
    };

    const int wm = wid & 3;
    const int wn = wid >> 2;

    wmma::fragment<wmma::accumulator, 16, 16, 16, float> acc[2][4];
    #pragma unroll
    for (int i = 0; i < 2; ++i)
        #pragma unroll
        for (int j = 0; j < 4; ++j)
            wmma::fill_fragment(acc[i][j], 0.f);

    load_chunk(0);
    load_chunk(1);

    for (int c = 0; c < NCHUNK; ++c) {
        if (c < NCHUNK - 1) cp_wait<1>(); else cp_wait<0>();
        __syncthreads();
        const char* stg = smem + (size_t)(c % 3) * STAGE_BYTES;
        const __half* As = (const __half*)(stg);
        const __half* Bs = (const __half*)(stg + OFF_B);
        #pragma unroll
        for (int ks = 0; ks < 2; ++ks) {
            wmma::fragment<wmma::matrix_a, 16, 16, 16, __half, wmma::row_major> af[2];
            #pragma unroll
            for (int i = 0; i < 2; ++i)
                wmma::load_matrix_sync(af[i], As + (wm*32 + i*16)*A_STRIDE + ks*16, A_STRIDE);
            #pragma unroll
            for (int j = 0; j < 4; ++j) {
                wmma::fragment<wmma::matrix_b, 16, 16, 16, __half, wmma::row_major> bf;
                wmma::load_matrix_sync(bf, Bs + (ks*16)*B_STRIDE + wn*64 + j*16, B_STRIDE);
                #pragma unroll
                for (int i = 0; i < 2; ++i)
                    wmma::mma_sync(acc[i][j], af[i], bf, acc[i][j]);
            }
        }
        if (c + 2 < NCHUNK) load_chunk(c + 2);
    }

    __syncthreads();
    #pragma unroll
    for (int i = 0; i < 2; ++i)
        #pragma unroll
        for (int j = 0; j < 4; ++j)
            wmma::store_matrix_sync(Cs + (size_t)(wm*32 + i*16)*C_STRIDE + wn*64 + j*16,
                                    acc[i][j], C_STRIDE, wmma::mem_row_major);
    __syncthreads();

    #pragma unroll
    for (int rr = 0; rr < 8; ++rr) {
        const int row = wid*8 + rr;
        float v[8];
        float s = 0.f, ss = 0.f;
        #pragma unroll
        for (int j = 0; j < 8; ++j) {
            v[j] = Cs[(size_t)row*C_STRIDE + lane + j*32] + par[lane + j*32];
            s  += v[j];
            ss += v[j]*v[j];
        }
        #pragma unroll
        for (int o = 16; o > 0; o >>= 1) {
            s  += __shfl_xor_sync(0xffffffffu, s,  o);
            ss += __shfl_xor_sync(0xffffffffu, ss, o);
        }
        const float mu = s * (1.f/FF);
        const float rs = rsqrtf(ss * (1.f/FF) - mu*mu + EPSF);

        if (!STAGE) {
            size_t ro = ((size_t)(b*(TT+2) + t0 + 1 + row))*FF;
            #pragma unroll
            for (int j = 0; j < 8; ++j) {
                int cch = lane + j*32;
                float w = fmaf((v[j] - mu)*rs, par[256 + cch], par[512 + cch]);
                g_h1[ro + cch] = __float2half(fmaxf(w, 0.f));
            }
        } else {
            float dot = 0.f;
            #pragma unroll
            for (int j = 0; j < 8; ++j) {
                int cch = lane + j*32;
                float w = fmaf((v[j] - mu)*rs, par[256 + cch], par[512 + cch]);
                dot = fmaf(fmaxf(w, 0.f), par[768 + cch], dot);
            }
            #pragma unroll
            for (int o = 16; o > 0; o >>= 1)
                dot += __shfl_xor_sync(0xffffffffu, dot, o);
            if (lane == 0)
                dur_out[b*TT + t0 + row] = fmaxf(dot + lin_b[0], 0.f);
        }
    }
}

// ---------------- gather: 2 rows per thread, idx loads hoisted ----------------
__device__ __forceinline__ void st_cs(float4* p, float4 v) {
    asm volatile("st.global.cs.v4.f32 [%0], {%1,%2,%3,%4};"
                 :: "l"(p), "f"(v.x), "f"(v.y), "f"(v.z), "f"(v.w) : "memory");
}
#define NROWS  (BB*MEL)          // 73728
#define HROWS  (NROWS/2)         // 36864
__global__ void gather_k(const float* __restrict__ x, float* __restrict__ out) {
    const long long u  = (long long)blockIdx.x * blockDim.x + threadIdx.x;
    const long long NU = (long long)HROWS * 32;
    if (u >= NU) return;
    const int c8 = (int)(u & 31);
    const long long rowa = u >> 5;
    const long long rowb = rowa + HROWS;
    const int ba = (int)(rowa / MEL);
    const int bb = (int)(rowb / MEL);
    const int ia = __ldg(&g_idx[rowa]);
    const int ib = __ldg(&g_idx[rowb]);
    float4 a0 = make_float4(0.f,0.f,0.f,0.f), a1 = a0, b0 = a0, b1 = a0;
    if (ia >= 0) {
        const float4* s = reinterpret_cast<const float4*>(x) + ((long long)ba*TT + ia)*(DD/4) + c8*2;
        a0 = __ldg(s); a1 = __ldg(s + 1);
    }
    if (ib >= 0) {
        const float4* s = reinterpret_cast<const float4*>(x) + ((long long)bb*TT + ib)*(DD/4) + c8*2;
        b0 = __ldg(s); b1 = __ldg(s + 1);
    }
    float4* da = reinterpret_cast<float4*>(out) + rowa*(DD/4) + c8*2;
    float4* db = reinterpret_cast<float4*>(out) + rowb*(DD/4) + c8*2;
    st_cs(da, a0); st_cs(da + 1, a1);
    st_cs(db, b0); st_cs(db + 1, b1);
}

// ---------------- launch: fused prep, then fork/join ----------------
extern "C" void kernel_launch(void* const* d_in, const int* in_sizes, int n_in,
                              void* d_out, int out_size) {
    int base = 2;
    if (n_in >= 13 && in_sizes[2] == 1) base = 3;

    const float* x      = (const float*)d_in[0];
    const int*   target = (const int*)  d_in[1];
    const float* c1w = (const float*)d_in[base + 0];
    const float* c1b = (const float*)d_in[base + 1];
    const float* l1g = (const float*)d_in[base + 2];
    const float* l1b = (const float*)d_in[base + 3];
    const float* c2w = (const float*)d_in[base + 4];
    const float* c2b = (const float*)d_in[base + 5];
    const float* l2g = (const float*)d_in[base + 6];
    const float* l2b = (const float*)d_in[base + 7];
    const float* lw  = (const float*)d_in[base + 8];
    const float* lb  = (const float*)d_in[base + 9];

    float* out = (float*)d_out;
    float* dur = out + (size_t)BB * MEL * DD;

    cudaFuncSetAttribute(conv_wmma<0>, cudaFuncAttributeMaxDynamicSharedMemorySize, SMEM_BYTES);
    cudaFuncSetAttribute(conv_wmma<1>, cudaFuncAttributeMaxDynamicSharedMemorySize, SMEM_BYTES);
    cudaFuncSetAttribute(prep_fused,   cudaFuncAttributeMaxDynamicSharedMemorySize, PREP_SMEM);

    const long long NU = (long long)HROWS * 32;
    const int gatherBlocks = (int)((NU + 255)/256);

    cudaStream_t s2 = nullptr;
    cudaEvent_t eFork = nullptr, eJoin = nullptr;
    bool forked = (cudaStreamCreateWithFlags(&s2, cudaStreamNonBlocking) == cudaSuccess)
               && (cudaEventCreateWithFlags(&eFork, cudaEventDisableTiming) == cudaSuccess)
               && (cudaEventCreateWithFlags(&eJoin, cudaEventDisableTiming) == cudaSuccess);

    if (forked) {
        // shared prefix on default stream
        prep_fused<<<48 + NXBLK, 512, PREP_SMEM>>>(x, c1w, c2w, target);
        cudaEventRecord(eFork, 0);
        // chain B on s2
        cudaStreamWaitEvent(s2, eFork, 0);
        gather_k<<<gatherBlocks, 256, 0, s2>>>(x, out);
        cudaEventRecord(eJoin, s2);
        // chain A on default stream
        conv_wmma<0><<<BB*NTILES, TPB, SMEM_BYTES>>>(c1b, l1g, l1b, lw, lb, nullptr);
        conv_wmma<1><<<BB*NTILES, TPB, SMEM_BYTES>>>(c2b, l2g, l2b, lw, lb, dur);
        cudaStreamWaitEvent(0, eJoin, 0);

        cudaEventDestroy(eFork);
        cudaEventDestroy(eJoin);
        cudaStreamDestroy(s2);
    } else {
        if (s2)    cudaStreamDestroy(s2);
        if (eFork) cudaEventDestroy(eFork);
        if (eJoin) cudaEventDestroy(eJoin);

        prep_fused<<<48 + NXBLK, 512, PREP_SMEM>>>(x, c1w, c2w, target);
        gather_k<<<gatherBlocks, 256>>>(x, out);
        conv_wmma<0><<<BB*NTILES, TPB, SMEM_BYTES>>>(c1b, l1g, l1b, lw, lb, nullptr);
        conv_wmma<1><<<BB*NTILES, TPB, SMEM_BYTES>>>(c2b, l2g, l2b, lw, lb, dur);
    }
}

// round 11
// speedup vs baseline: 3.7158x; 1.0036x over previous
#include <cuda_runtime.h>
#include <cuda_fp16.h>
#include <mma.h>
#include <cstdint>

using namespace nvcuda;

#define BB   32
#define TT   512
#define DD   256
#define FF   256
#define MEL  2304
#define EPSF 1e-5f

#define TPB    512      // 16 warps
#define NCHUNK 24       // K=768 in chunks of 32
#define MTILE  128      // tokens per block
#define NTILES 4        // tiles per batch -> 128 blocks total

// ---------------- device scratch ----------------
__device__ __align__(128) __half g_xpad [(size_t)BB*(TT+2)*DD];   // fp16 x (padded)
__device__ __align__(128) __half g_h1   [(size_t)BB*(TT+2)*FF];   // fp16 h1 (padded)
__device__ __align__(128) __half g_wB   [2*768*256];              // [stage][kcol][f] fp16
__device__ int g_idx[BB*MEL];

// ---------------- conv smem layout (bytes) ----------------
#define STAGE_BYTES 27136
#define OFF_B    10240
#define OFF_PAR  135168
#define SMEM_BYTES 139264
#define A_STRIDE 40
#define B_STRIDE 264
#define C_STRIDE 264

__device__ __forceinline__ uint32_t smem_u32(const void* p) {
    uint32_t a;
    asm("{ .reg .u64 t; cvta.to.shared.u64 t, %1; cvt.u32.u64 %0, t; }" : "=r"(a) : "l"(p));
    return a;
}
__device__ __forceinline__ void cp16(uint32_t dst, const void* src) {
    asm volatile("cp.async.cg.shared.global [%0], [%1], 16;" :: "r"(dst), "l"(src));
}
__device__ __forceinline__ void cp_commit() { asm volatile("cp.async.commit_group;" ::: "memory"); }
template<int N> __device__ __forceinline__ void cp_wait() { asm volatile("cp.async.wait_group %0;" :: "n"(N) : "memory"); }

// ---------------- cum_idx: cumsum + searchsorted (runs first on stream 2) ----------------
__global__ __launch_bounds__(512)
void cum_idx(const int* __restrict__ target) {
    __shared__ int cs[TT];
    __shared__ int wsum[16];
    const int b = blockIdx.x, t = threadIdx.x;
    const int wid = t >> 5, lid = t & 31;
    int sc = target[b*TT + t];
    #pragma unroll
    for (int o = 1; o < 32; o <<= 1) {
        int n = __shfl_up_sync(0xffffffffu, sc, o);
        if (lid >= o) sc += n;
    }
    if (lid == 31) wsum[wid] = sc;
    __syncthreads();
    if (wid == 0 && lid < 16) {
        int w = wsum[lid];
        #pragma unroll
        for (int o = 1; o < 16; o <<= 1) {
            int n = __shfl_up_sync(0xffffu, w, o);
            if (lid >= o) w += n;
        }
        wsum[lid] = w;
    }
    __syncthreads();
    cs[t] = sc + (wid ? wsum[wid-1] : 0);
    __syncthreads();
    const int total = cs[TT-1];
    for (int to = t; to < MEL; to += TT) {
        int lo = 0, hi = TT;
        while (lo < hi) {
            int mid = (lo + hi) >> 1;
            if (cs[mid] <= to) lo = mid + 1; else hi = mid;
        }
        g_idx[b*MEL + to] = (to < total) ? min(lo, TT-1) : -1;
    }
}

// ---------------- prep_xw: w transpose (16 blocks) | x convert (516 blocks) ----------------
#define PW_PITCH 778                      // halves; lane stride 389 words, gcd(389,32)=1
#define PREP_SMEM (32*PW_PITCH*2)         // 49792 B
#define NXBLK 516
#define NTOTX (BB*(TT+2)*DD)

__global__ __launch_bounds__(512)
void prep_xw(const float* __restrict__ x,
             const float* __restrict__ w1,
             const float* __restrict__ w2) {
    extern __shared__ char dsm[];
    const int j   = blockIdx.x;
    const int tid = threadIdx.x;
    const int wid = tid >> 5, lane = tid & 31;

    if (j < 16) {
        // ---- prep_w: transpose 32 f-rows x 768 m-cols, coalesced both sides ----
        const int stg   = j >> 3;
        const int f0    = (j & 7) * 32;
        const float* w  = stg ? w2 : w1;
        __half* S = (__half*)dsm;       // S[f_local][m], pitch PW_PITCH halves
        #pragma unroll
        for (int it = 0; it < 12; ++it) {
            int u  = tid + it*512;       // 0..6143
            int r  = u / 192;
            int m  = (u % 192) * 4;
            float4 v = __ldg((const float4*)(w + (size_t)(f0 + r)*768 + m));
            __half* dst = S + r*PW_PITCH + m;
            dst[0] = __float2half(v.x);
            dst[1] = __float2half(v.y);
            dst[2] = __float2half(v.z);
            dst[3] = __float2half(v.w);
        }
        __syncthreads();
        for (int i = 0; i < 48; ++i) {
            int kcol = wid*48 + i;
            int k = kcol >> 8, d = kcol & 255;
            int m = d*3 + k;
            g_wB[((size_t)(stg*768 + kcol))*256 + f0 + lane] = S[lane*PW_PITCH + m];
        }
    } else {
        // ---- prep_x + h1 edge zero ----
        const int bb = j - 16;
        #pragma unroll
        for (int it = 0; it < 16; ++it) {
            int i = (bb*16 + it)*512 + tid;
            if (i < NTOTX) {
                int d   = i & (DD-1);
                int row = i >> 8;
                int t   = row % (TT+2);
                int b   = row / (TT+2);
                float v = (t == 0 || t == TT+1) ? 0.f : x[((size_t)(b*TT + t - 1))*DD + d];
                g_xpad[i] = __float2half(v);
            }
        }
        if (bb == 0) {
            #pragma unroll
            for (int it = 0; it < 32; ++it) {
                int i = it*512 + tid;       // 0..16383
                int d = i & (FF-1);
                int r = i >> 8;
                int b = r >> 1;
                int t = (r & 1) ? (TT+1) : 0;
                g_h1[((size_t)(b*(TT+2) + t))*FF + d] = __float2half(0.f);
            }
        }
    }
}

// ---------------- fused conv(K=3) fp16 WMMA GEMM + bias + LN + ReLU (+linear) ----------------
// __launch_bounds__(576): cap regs at 112/thread so a gather block (256thr x 24reg)
// can co-reside on the same SM -> real fork/join overlap.
template<int STAGE>
__global__ __launch_bounds__(576, 1)
void conv_wmma(const float* __restrict__ bias,
               const float* __restrict__ gamma,
               const float* __restrict__ beta,
               const float* __restrict__ lin_w,
               const float* __restrict__ lin_b,
               float* __restrict__ dur_out) {
    extern __shared__ char smem[];
    const uint32_t sbase = smem_u32(smem);
    const int tid  = threadIdx.x;
    const int wid  = tid >> 5;
    const int lane = tid & 31;
    const int b    = blockIdx.x >> 2;
    const int t0   = (blockIdx.x & 3) * MTILE;

    const __half* __restrict__ srcA = STAGE ? g_h1 : g_xpad;
    float* Cs  = (float*)smem;
    float* par = (float*)(smem + OFF_PAR);

    if (tid < 256) {
        par[tid]       = bias [tid];
        par[256 + tid] = gamma[tid];
        par[512 + tid] = beta [tid];
        par[768 + tid] = STAGE ? lin_w[tid] : 0.f;
    }

    auto load_chunk = [&](int c) {
        const uint32_t st = sbase + (uint32_t)(c % 3) * STAGE_BYTES;
        const int k   = c >> 3;
        const int d0  = (c & 7) * 32;
        {
            int r = tid >> 2, seg = tid & 3;
            size_t go = ((size_t)(b*(TT+2) + t0 + k + r))*DD + d0 + seg*8;
            cp16(st + r*(A_STRIDE*2) + seg*16, srcA + go);
        }
        {
            const size_t bbase = ((size_t)(STAGE*768 + c*32))*256;
            #pragma unroll
            for (int it = 0; it < 2; ++it) {
                int u = tid + it*TPB;
                int r = u >> 5, seg = u & 31;
                cp16(st + OFF_B + r*(B_STRIDE*2) + seg*16, g_wB + bbase + (size_t)r*256 + seg*8);
            }
        }
        cp_commit();
    };

    const int wm = wid & 3;
    const int wn = wid >> 2;

    wmma::fragment<wmma::accumulator, 16, 16, 16, float> acc[2][4];
    #pragma unroll
    for (int i = 0; i < 2; ++i)
        #pragma unroll
        for (int j = 0; j < 4; ++j)
            wmma::fill_fragment(acc[i][j], 0.f);

    load_chunk(0);
    load_chunk(1);

    for (int c = 0; c < NCHUNK; ++c) {
        if (c < NCHUNK - 1) cp_wait<1>(); else cp_wait<0>();
        __syncthreads();
        const char* stg = smem + (size_t)(c % 3) * STAGE_BYTES;
        const __half* As = (const __half*)(stg);
        const __half* Bs = (const __half*)(stg + OFF_B);
        #pragma unroll
        for (int ks = 0; ks < 2; ++ks) {
            wmma::fragment<wmma::matrix_a, 16, 16, 16, __half, wmma::row_major> af[2];
            #pragma unroll
            for (int i = 0; i < 2; ++i)
                wmma::load_matrix_sync(af[i], As + (wm*32 + i*16)*A_STRIDE + ks*16, A_STRIDE);
            #pragma unroll
            for (int j = 0; j < 4; ++j) {
                wmma::fragment<wmma::matrix_b, 16, 16, 16, __half, wmma::row_major> bf;
                wmma::load_matrix_sync(bf, Bs + (ks*16)*B_STRIDE + wn*64 + j*16, B_STRIDE);
                #pragma unroll
                for (int i = 0; i < 2; ++i)
                    wmma::mma_sync(acc[i][j], af[i], bf, acc[i][j]);
            }
        }
        if (c + 2 < NCHUNK) load_chunk(c + 2);
    }

    __syncthreads();
    #pragma unroll
    for (int i = 0; i < 2; ++i)
        #pragma unroll
        for (int j = 0; j < 4; ++j)
            wmma::store_matrix_sync(Cs + (size_t)(wm*32 + i*16)*C_STRIDE + wn*64 + j*16,
                                    acc[i][j], C_STRIDE, wmma::mem_row_major);
    __syncthreads();

    #pragma unroll
    for (int rr = 0; rr < 8; ++rr) {
        const int row = wid*8 + rr;
        float v[8];
        float s = 0.f, ss = 0.f;
        #pragma unroll
        for (int j = 0; j < 8; ++j) {
            v[j] = Cs[(size_t)row*C_STRIDE + lane + j*32] + par[lane + j*32];
            s  += v[j];
            ss += v[j]*v[j];
        }
        #pragma unroll
        for (int o = 16; o > 0; o >>= 1) {
            s  += __shfl_xor_sync(0xffffffffu, s,  o);
            ss += __shfl_xor_sync(0xffffffffu, ss, o);
        }
        const float mu = s * (1.f/FF);
        const float rs = rsqrtf(ss * (1.f/FF) - mu*mu + EPSF);

        if (!STAGE) {
            size_t ro = ((size_t)(b*(TT+2) + t0 + 1 + row))*FF;
            #pragma unroll
            for (int j = 0; j < 8; ++j) {
                int cch = lane + j*32;
                float w = fmaf((v[j] - mu)*rs, par[256 + cch], par[512 + cch]);
                g_h1[ro + cch] = __float2half(fmaxf(w, 0.f));
            }
        } else {
            float dot = 0.f;
            #pragma unroll
            for (int j = 0; j < 8; ++j) {
                int cch = lane + j*32;
                float w = fmaf((v[j] - mu)*rs, par[256 + cch], par[512 + cch]);
                dot = fmaf(fmaxf(w, 0.f), par[768 + cch], dot);
            }
            #pragma unroll
            for (int o = 16; o > 0; o >>= 1)
                dot += __shfl_xor_sync(0xffffffffu, dot, o);
            if (lane == 0)
                dur_out[b*TT + t0 + row] = fmaxf(dot + lin_b[0], 0.f);
        }
    }
}

// ---------------- gather: 2 rows per thread, idx loads hoisted ----------------
__device__ __forceinline__ void st_cs(float4* p, float4 v) {
    asm volatile("st.global.cs.v4.f32 [%0], {%1,%2,%3,%4};"
                 :: "l"(p), "f"(v.x), "f"(v.y), "f"(v.z), "f"(v.w) : "memory");
}
#define NROWS  (BB*MEL)          // 73728
#define HROWS  (NROWS/2)         // 36864
__global__ __launch_bounds__(256)
void gather_k(const float* __restrict__ x, float* __restrict__ out) {
    const long long u  = (long long)blockIdx.x * blockDim.x + threadIdx.x;
    const long long NU = (long long)HROWS * 32;
    if (u >= NU) return;
    const int c8 = (int)(u & 31);
    const long long rowa = u >> 5;
    const long long rowb = rowa + HROWS;
    const int ba = (int)(rowa / MEL);
    const int bb = (int)(rowb / MEL);
    const int ia = __ldg(&g_idx[rowa]);
    const int ib = __ldg(&g_idx[rowb]);
    float4 a0 = make_float4(0.f,0.f,0.f,0.f), a1 = a0, b0 = a0, b1 = a0;
    if (ia >= 0) {
        const float4* s = reinterpret_cast<const float4*>(x) + ((long long)ba*TT + ia)*(DD/4) + c8*2;
        a0 = __ldg(s); a1 = __ldg(s + 1);
    }
    if (ib >= 0) {
        const float4* s = reinterpret_cast<const float4*>(x) + ((long long)bb*TT + ib)*(DD/4) + c8*2;
        b0 = __ldg(s); b1 = __ldg(s + 1);
    }
    float4* da = reinterpret_cast<float4*>(out) + rowa*(DD/4) + c8*2;
    float4* db = reinterpret_cast<float4*>(out) + rowb*(DD/4) + c8*2;
    st_cs(da, a0); st_cs(da + 1, a1);
    st_cs(db, b0); st_cs(db + 1, b1);
}

// ---------------- launch ----------------
extern "C" void kernel_launch(void* const* d_in, const int* in_sizes, int n_in,
                              void* d_out, int out_size) {
    int base = 2;
    if (n_in >= 13 && in_sizes[2] == 1) base = 3;

    const float* x      = (const float*)d_in[0];
    const int*   target = (const int*)  d_in[1];
    const float* c1w = (const float*)d_in[base + 0];
    const float* c1b = (const float*)d_in[base + 1];
    const float* l1g = (const float*)d_in[base + 2];
    const float* l1b = (const float*)d_in[base + 3];
    const float* c2w = (const float*)d_in[base + 4];
    const float* c2b = (const float*)d_in[base + 5];
    const float* l2g = (const float*)d_in[base + 6];
    const float* l2b = (const float*)d_in[base + 7];
    const float* lw  = (const float*)d_in[base + 8];
    const float* lb  = (const float*)d_in[base + 9];

    float* out = (float*)d_out;
    float* dur = out + (size_t)BB * MEL * DD;

    cudaFuncSetAttribute(conv_wmma<0>, cudaFuncAttributeMaxDynamicSharedMemorySize, SMEM_BYTES);
    cudaFuncSetAttribute(conv_wmma<1>, cudaFuncAttributeMaxDynamicSharedMemorySize, SMEM_BYTES);
    cudaFuncSetAttribute(prep_xw,      cudaFuncAttributeMaxDynamicSharedMemorySize, PREP_SMEM);

    const long long NU = (long long)HROWS * 32;
    const int gatherBlocks = (int)((NU + 255)/256);

    cudaStream_t s2 = nullptr;
    cudaEvent_t eFork = nullptr, eJoin = nullptr;
    bool forked = (cudaStreamCreateWithFlags(&s2, cudaStreamNonBlocking) == cudaSuccess)
               && (cudaEventCreateWithFlags(&eFork, cudaEventDisableTiming) == cudaSuccess)
               && (cudaEventCreateWithFlags(&eJoin, cudaEventDisableTiming) == cudaSuccess);

    if (forked) {
        cudaEventRecord(eFork, 0);
        // chain B on s2: cum_idx first (tiny), gather spans the conv window
        cudaStreamWaitEvent(s2, eFork, 0);
        cum_idx<<<BB, TT, 0, s2>>>(target);
        gather_k<<<gatherBlocks, 256, 0, s2>>>(x, out);
        cudaEventRecord(eJoin, s2);
        // chain A on default stream
        prep_xw<<<16 + NXBLK, 512, PREP_SMEM>>>(x, c1w, c2w);
        conv_wmma<0><<<BB*NTILES, TPB, SMEM_BYTES>>>(c1b, l1g, l1b, lw, lb, nullptr);
        conv_wmma<1><<<BB*NTILES, TPB, SMEM_BYTES>>>(c2b, l2g, l2b, lw, lb, dur);
        cudaStreamWaitEvent(0, eJoin, 0);

        cudaEventDestroy(eFork);
        cudaEventDestroy(eJoin);
        cudaStreamDestroy(s2);
    } else {
        if (s2)    cudaStreamDestroy(s2);
        if (eFork) cudaEventDestroy(eFork);
        if (eJoin) cudaEventDestroy(eJoin);

        cum_idx<<<BB, TT>>>(target);
        prep_xw<<<16 + NXBLK, 512, PREP_SMEM>>>(x, c1w, c2w);
        gather_k<<<gatherBlocks, 256>>>(x, out);
        conv_wmma<0><<<BB*NTILES, TPB, SMEM_BYTES>>>(c1b, l1g, l1b, lw, lb, nullptr);
        conv_wmma<1><<<BB*NTILES, TPB, SMEM_BYTES>>>(c2b, l2g, l2b, lw, lb, dur);
    }
}